// round 13
// baseline (speedup 1.0000x reference)
#include <cuda_runtime.h>
#include <cuda_bf16.h>
#include <cstdint>

#define NTHREADS 512
#define MROWS    256
#define SA 336            // act / W1 / W2a row stride in BYTES (168 bf16)
#define SW 272            // stage(f32x68) / wt / W2B / D11B row stride in BYTES

// ---------------- SMEM byte layout ----------------
#define OFF_W1    0        // bf16 [64 x 168]: C1_hi D12_hi | C1_lo D12_lo
#define OFF_W2A   21504    // bf16 [64 x 168]: A_hi  B2_hi  | A_lo  B2_lo
#define OFF_W2B   43008    // bf16 [64 x 136]: B1_hi | B1_lo
#define OFF_D11B  60416    // bf16 [48 x 136]: D11 rows 16..63, hi | lo
#define OFF_BV    73472    // f32 [64]
#define OFF_BX    73728    // f32 [64]
#define OFF_ACT   73984    // bf16 [256 x 168]: x_hi | u_hi | x_lo | u_lo
#define OFF_S     160000   // ALIASED: stage f32[256 x 68] / wt bf16 [hi_b|lo_b] at byte 64b
#define SMEM_BYTES 229632

__device__ __align__(16) unsigned char gW1s  [21504];
__device__ __align__(16) unsigned char gW2As [21504];
__device__ __align__(16) unsigned char gW2Bs [17408];
__device__ __align__(16) unsigned char gD11Bs[13056];

__device__ __forceinline__ uint32_t smem_u32(const void* p) {
    uint32_t a;
    asm("{ .reg .u64 t; cvta.to.shared.u64 t, %1; cvt.u32.u64 %0, t; }" : "=r"(a) : "l"(p));
    return a;
}
__device__ __forceinline__ void ldsm4(unsigned r[4], uint32_t addr) {
    asm volatile("ldmatrix.sync.aligned.m8n8.x4.shared.b16 {%0,%1,%2,%3}, [%4];"
        : "=r"(r[0]), "=r"(r[1]), "=r"(r[2]), "=r"(r[3]) : "r"(addr));
}
__device__ __forceinline__ void mma16816(float* d, const unsigned* a, unsigned b0, unsigned b1) {
    asm volatile("mma.sync.aligned.m16n8k16.row.col.f32.bf16.bf16.f32 "
        "{%0,%1,%2,%3},{%4,%5,%6,%7},{%8,%9},{%0,%1,%2,%3};"
        : "+f"(d[0]), "+f"(d[1]), "+f"(d[2]), "+f"(d[3])
        : "r"(a[0]), "r"(a[1]), "r"(a[2]), "r"(a[3]), "r"(b0), "r"(b1));
}
// two row-tiles (a0: rows 0-15, a1: rows 16-31) against one 16-col B frag pair
__device__ __forceinline__ void mma_2t(float (*acc)[4][4], int jp,
                                       const unsigned* a0, const unsigned* a1,
                                       const unsigned* bf) {
    mma16816(acc[0][2*jp],     a0, bf[0], bf[2]);
    mma16816(acc[0][2*jp + 1], a0, bf[1], bf[3]);
    mma16816(acc[1][2*jp],     a1, bf[0], bf[2]);
    mma16816(acc[1][2*jp + 1], a1, bf[1], bf[3]);
}
__device__ __forceinline__ void split2(float a, float b, unsigned& hi, unsigned& lo) {
    const __nv_bfloat16 ha = __float2bfloat16_rn(a), hb = __float2bfloat16_rn(b);
    hi = (unsigned)(*reinterpret_cast<const unsigned short*>(&ha))
       | ((unsigned)(*reinterpret_cast<const unsigned short*>(&hb)) << 16);
    const __nv_bfloat162 t = __floats2bfloat162_rn(a - __bfloat162float(ha),
                                                   b - __bfloat162float(hb));
    lo = *reinterpret_cast<const unsigned*>(&t);
}

// ---------------- prep kernel (8 CTAs) ----------------
__global__ void __launch_bounds__(128)
renl2_prep_kernel(const float* __restrict__ gA,  const float* __restrict__ gB1,
                  const float* __restrict__ gB2, const float* __restrict__ gC1,
                  const float* __restrict__ gD11,const float* __restrict__ gD12)
{
    const int tid = blockIdx.x * 128 + threadIdx.x;
    #pragma unroll 1
    for (int idx = tid; idx < 64 * 40; idx += 1024) {
        const int n = idx / 40, k = (idx - n * 40) * 2;
        float v1a, v1b, v2a, v2b;
        if (k < 64) { v1a = gC1[n*64 + k]; v1b = gC1[n*64 + k + 1];
                      v2a = gA [n*64 + k]; v2b = gA [n*64 + k + 1]; }
        else        { v1a = gD12[n*16 + k - 64]; v1b = gD12[n*16 + k - 63];
                      v2a = gB2 [n*16 + k - 64]; v2b = gB2 [n*16 + k - 63]; }
        unsigned h1, l1, h2, l2;
        split2(v1a, v1b, h1, l1);
        split2(v2a, v2b, h2, l2);
        *reinterpret_cast<unsigned*>(gW1s  + n*SA + 2*k)       = h1;
        *reinterpret_cast<unsigned*>(gW1s  + n*SA + 160 + 2*k) = l1;
        *reinterpret_cast<unsigned*>(gW2As + n*SA + 2*k)       = h2;
        *reinterpret_cast<unsigned*>(gW2As + n*SA + 160 + 2*k) = l2;
    }
    #pragma unroll 1
    for (int idx = tid; idx < 64 * 32; idx += 1024) {
        const int n = idx >> 5, k = (idx & 31) * 2;
        unsigned h, l;
        split2(gB1[n*64 + k], gB1[n*64 + k + 1], h, l);
        *reinterpret_cast<unsigned*>(gW2Bs + n*SW + 2*k)       = h;
        *reinterpret_cast<unsigned*>(gW2Bs + n*SW + 128 + 2*k) = l;
    }
    #pragma unroll 1
    for (int idx = tid; idx < 48 * 32; idx += 1024) {
        const int nl = idx >> 5, k = (idx & 31) * 2, n = nl + 16;
        unsigned h, l;
        split2(gD11[n*64 + k], gD11[n*64 + k + 1], h, l);
        *reinterpret_cast<unsigned*>(gD11Bs + nl*SW + 2*k)       = h;
        *reinterpret_cast<unsigned*>(gD11Bs + nl*SW + 128 + 2*k) = l;
    }
}

// ---------------- main kernel ----------------
__global__ void __launch_bounds__(NTHREADS, 1)
renl2_hmma_kernel(const float* __restrict__ gx,  const float* __restrict__ gu,
                  const float* __restrict__ gD11,
                  const float* __restrict__ gbv, const float* __restrict__ gbx,
                  float* __restrict__ gout, int N)
{
    extern __shared__ char smem[];
    const uint32_t sbase = smem_u32(smem);
    const int tid  = threadIdx.x;
    const int lane = tid & 31;
    const int wid  = tid >> 5;
    const int pair = wid >> 1;          // 0..7, owns rows 32*pair..+31
    const int sub  = wid & 1;           // n-half: cols 32*sub..+31
    const int R0   = 32 * pair;
    const int rowbase = blockIdx.x * MROWS;

    float* stage = reinterpret_cast<float*>(smem + OFF_S);
    float* sbv   = reinterpret_cast<float*>(smem + OFF_BV);
    float* sbx   = reinterpret_cast<float*>(smem + OFF_BX);

    // ---------- copy pre-split weights + biases ----------
    {
        const uint4* s1 = reinterpret_cast<const uint4*>(gW1s);
        const uint4* s2 = reinterpret_cast<const uint4*>(gW2As);
        uint4* d1 = reinterpret_cast<uint4*>(smem + OFF_W1);
        uint4* d2 = reinterpret_cast<uint4*>(smem + OFF_W2A);
        #pragma unroll 1
        for (int i = tid; i < 21504/16; i += NTHREADS) { d1[i] = s1[i]; d2[i] = s2[i]; }
        const uint4* s3 = reinterpret_cast<const uint4*>(gW2Bs);
        uint4* d3 = reinterpret_cast<uint4*>(smem + OFF_W2B);
        #pragma unroll 1
        for (int i = tid; i < 17408/16; i += NTHREADS) d3[i] = s3[i];
        const uint4* s4 = reinterpret_cast<const uint4*>(gD11Bs);
        uint4* d4 = reinterpret_cast<uint4*>(smem + OFF_D11B);
        #pragma unroll 1
        for (int i = tid; i < 13056/16; i += NTHREADS) d4[i] = s4[i];
        if (tid >= 64 && tid < 128)  sbv[tid - 64]  = gbv[tid - 64];
        if (tid >= 128 && tid < 192) sbx[tid - 128] = gbx[tid - 128];
    }

    // ---------- stage activations (hi/lo split) ----------
    const float4* gx4 = reinterpret_cast<const float4*>(gx);
    #pragma unroll 1
    for (int idx = tid; idx < MROWS * 16; idx += NTHREADS) {
        const int row = idx >> 4, q0 = idx & 15;
        if (rowbase + row >= N) continue;
        const float4 v = gx4[(size_t)(rowbase + row) * 16 + q0];
        unsigned h0, l0, h1, l1;
        split2(v.x, v.y, h0, l0);
        split2(v.z, v.w, h1, l1);
        char* rp = smem + OFF_ACT + row * SA;
        *reinterpret_cast<uint2*>(rp + 8*q0)       = make_uint2(h0, h1);
        *reinterpret_cast<uint2*>(rp + 160 + 8*q0) = make_uint2(l0, l1);
    }
    const float4* gu4 = reinterpret_cast<const float4*>(gu);
    #pragma unroll 1
    for (int idx = tid; idx < MROWS * 4; idx += NTHREADS) {
        const int row = idx >> 2, q0 = idx & 3;
        if (rowbase + row >= N) continue;
        const float4 v = gu4[(size_t)(rowbase + row) * 4 + q0];
        unsigned h0, l0, h1, l1;
        split2(v.x, v.y, h0, l0);
        split2(v.z, v.w, h1, l1);
        char* rp = smem + OFF_ACT + row * SA;
        *reinterpret_cast<uint2*>(rp + 128 + 8*q0) = make_uint2(h0, h1);
        *reinterpret_cast<uint2*>(rp + 288 + 8*q0) = make_uint2(l0, l1);
    }
    __syncthreads();   // ONLY block-wide barrier

    // ---------- fragment addresses ----------
    const uint32_t a_act0 = sbase + OFF_ACT + (R0 + (lane & 15)) * SA + 16 * (lane >> 4);
    const uint32_t a_act1 = a_act0 + 16 * SA;
    const uint32_t a_wt0  = sbase + OFF_S + (R0 + (lane & 15)) * SW + 16 * (lane >> 4);
    const uint32_t a_wt1  = a_wt0 + 16 * SW;
    const uint32_t bW1_0  = sbase + OFF_W1  + (32*sub + (lane & 15)) * SA + 16 * (lane >> 4);
    const uint32_t bW1_1  = bW1_0 + 16 * SA;
    const uint32_t bW2_0  = sbase + OFF_W2A + (32*sub + (lane & 15)) * SA + 16 * (lane >> 4);
    const uint32_t bW2_1  = bW2_0 + 16 * SA;
    const uint32_t bW2b_0 = sbase + OFF_W2B + (32*sub + (lane & 15)) * SW + 16 * (lane >> 4);
    const uint32_t bW2b_1 = bW2b_0 + 16 * SW;
    const uint32_t b_d11  = sbase + OFF_D11B + (lane & 15) * SW + 16 * (lane >> 4);

    const int q  = lane & 3;
    const int rh = lane >> 2;

    #define PBAR() asm volatile("bar.sync %0, 64;" :: "r"(pair + 8) : "memory")

    // acc[t][j][4]: row-tile t (16 rows), n-tile j (8 cols at 32*sub + 8*j)
    float acc [2][4][4] = {};     // w pre-activation (W1 path)
    float acc2[2][4][4] = {};     // out partial (W2a path)

    // ===== merged GEMM1 + GEMM2a, B-frags register-reused across hi/lo A =====
    #pragma unroll
    for (int c = 0; c < 5; c++) {
        unsigned ah0[4], ah1[4];
        ldsm4(ah0, a_act0 + 32*c);
        ldsm4(ah1, a_act1 + 32*c);
        unsigned b1h0[4], b1h1[4], b2h0[4], b2h1[4];
        ldsm4(b1h0, bW1_0 + 32*c);  ldsm4(b1h1, bW1_1 + 32*c);
        mma_2t(acc, 0, ah0, ah1, b1h0);  mma_2t(acc, 1, ah0, ah1, b1h1);   // hi.hi
        ldsm4(b2h0, bW2_0 + 32*c);  ldsm4(b2h1, bW2_1 + 32*c);
        mma_2t(acc2, 0, ah0, ah1, b2h0); mma_2t(acc2, 1, ah0, ah1, b2h1);
        {
            unsigned bl[4];
            ldsm4(bl, bW1_0 + 32*(5+c)); mma_2t(acc, 0, ah0, ah1, bl);     // hi.lo
            ldsm4(bl, bW1_1 + 32*(5+c)); mma_2t(acc, 1, ah0, ah1, bl);
            ldsm4(bl, bW2_0 + 32*(5+c)); mma_2t(acc2, 0, ah0, ah1, bl);
            ldsm4(bl, bW2_1 + 32*(5+c)); mma_2t(acc2, 1, ah0, ah1, bl);
        }
        unsigned al0[4], al1[4];
        ldsm4(al0, a_act0 + 32*(5+c));
        ldsm4(al1, a_act1 + 32*(5+c));
        mma_2t(acc, 0, al0, al1, b1h0);  mma_2t(acc, 1, al0, al1, b1h1);   // lo.hi
        mma_2t(acc2, 0, al0, al1, b2h0); mma_2t(acc2, 1, al0, al1, b2h1);
    }

    // spill helper (macro): write acc block (local jpair) to stage
    #define SPILL(JP) do {                                                   \
        _Pragma("unroll")                                                    \
        for (int t = 0; t < 2; t++)                                          \
            _Pragma("unroll")                                                \
            for (int jj = 2*(JP); jj <= 2*(JP)+1; jj++) {                    \
                float* bp = stage + (R0 + 16*t + rh) * 68 + 32*sub + 8*jj + 2*q; \
                bp[0] = acc[t][jj][0]; bp[1] = acc[t][jj][1];                \
                bp += 8 * 68;                                                \
                bp[0] = acc[t][jj][2]; bp[1] = acc[t][jj][3];                \
            }                                                                \
    } while (0)

    if (sub == 0) SPILL(0);     // block 0 (cols 0-15)
    PBAR();

    // ===== blocked solve: warp solves its 16 rows, col-halves split by sub =====
    #pragma unroll
    for (int b = 0; b < 4; b++) {
        if (lane < 16) {
            const int row = R0 + 16*sub + lane;
            float wv[16];
            const float4* srow = reinterpret_cast<const float4*>(stage + row * 68 + 16*b);
            const float4* bvp  = reinterpret_cast<const float4*>(sbv + 16*b);
            #pragma unroll
            for (int g = 0; g < 4; g++) {
                const float4 s = srow[g], v = bvp[g];
                wv[4*g+0] = s.x + v.x; wv[4*g+1] = s.y + v.y;
                wv[4*g+2] = s.z + v.z; wv[4*g+3] = s.w + v.w;
            }
            wv[0] = fmaxf(wv[0], 0.0f);
            #pragma unroll
            for (int il = 1; il < 16; il++) {
                const float4* dptr = reinterpret_cast<const float4*>(gD11 + (16*b + il) * 64 + 16*b);
                float a0 = wv[il], a1 = 0.0f, a2 = 0.0f, a3 = 0.0f;
                const int ng = (il + 3) >> 2;
                #pragma unroll
                for (int g = 0; g < 4; g++) {
                    if (g >= ng) break;                  // strict-lower zeros pad tail
                    const float4 d = dptr[g];
                    a0 = fmaf(d.x, wv[4*g+0], a0);
                    a1 = fmaf(d.y, wv[4*g+1], a1);
                    a2 = fmaf(d.z, wv[4*g+2], a2);
                    a3 = fmaf(d.w, wv[4*g+3], a3);
                }
                wv[il] = fmaxf((a0 + a1) + (a2 + a3), 0.0f);
            }
            char* wtp = smem + OFF_S + row * SW + 64*b;  // [hi(32B) | lo(32B)]
            unsigned hp[8], lp[8];
            #pragma unroll
            for (int t = 0; t < 8; t++) split2(wv[2*t], wv[2*t+1], hp[t], lp[t]);
            *reinterpret_cast<uint4*>(wtp)      = make_uint4(hp[0], hp[1], hp[2], hp[3]);
            *reinterpret_cast<uint4*>(wtp + 16) = make_uint4(hp[4], hp[5], hp[6], hp[7]);
            *reinterpret_cast<uint4*>(wtp + 32) = make_uint4(lp[0], lp[1], lp[2], lp[3]);
            *reinterpret_cast<uint4*>(wtp + 48) = make_uint4(lp[4], lp[5], lp[6], lp[7]);
        }
        PBAR();

        // --- HMMA update of still-pending blocks owned by this warp ---
        if (b < 3) {
            const bool work = (sub == 0) ? (b == 0) : true;
            if (work) {
                unsigned wh0[4], wh1[4], wl0[4], wl1[4];
                ldsm4(wh0, a_wt0 + 64*b);       ldsm4(wh1, a_wt1 + 64*b);
                ldsm4(wl0, a_wt0 + 64*b + 32);  ldsm4(wl1, a_wt1 + 64*b + 32);
                if (sub == 0) {
                    // target block 1 (local jp=1)
                    unsigned dh[4], dl[4];
                    const uint32_t dp = b_d11;   // p=1 -> offset 0
                    ldsm4(dh, dp + 32*b); ldsm4(dl, dp + 128 + 32*b);
                    mma_2t(acc, 1, wh0, wh1, dh);
                    mma_2t(acc, 1, wl0, wl1, dh);
                    mma_2t(acc, 1, wh0, wh1, dl);
                } else {
                    // targets: block 2 (jp=0) if b<2... block2 pending for b<=1; block3 always (b<3)
                    if (b <= 1) {
                        unsigned dh[4], dl[4];
                        const uint32_t dp = b_d11 + 1 * 16 * SW;   // p=2
                        ldsm4(dh, dp + 32*b); ldsm4(dl, dp + 128 + 32*b);
                        mma_2t(acc, 0, wh0, wh1, dh);
                        mma_2t(acc, 0, wl0, wl1, dh);
                        mma_2t(acc, 0, wh0, wh1, dl);
                    }
                    {
                        unsigned dh[4], dl[4];
                        const uint32_t dp = b_d11 + 2 * 16 * SW;   // p=3
                        ldsm4(dh, dp + 32*b); ldsm4(dl, dp + 128 + 32*b);
                        mma_2t(acc, 1, wh0, wh1, dh);
                        mma_2t(acc, 1, wl0, wl1, dh);
                        mma_2t(acc, 1, wh0, wh1, dl);
                    }
                }
            }
            // spills: block b+1 becomes final after this update round
            if (sub == 0 && b == 0) SPILL(1);            // block 1
            if (sub == 1 && b == 1) SPILL(0);            // block 2 (local jp 0)
            if (sub == 1 && b == 2) SPILL(1);            // block 3
            PBAR();
        }
    }
    PBAR();   // all wt rows written before GEMM2b reads both row-tiles

    // ===== GEMM2b: acc2 += [w] x B1^T (B-frags register-reused) =====
    #pragma unroll
    for (int c = 0; c < 4; c++) {
        unsigned wh0[4], wh1[4];
        ldsm4(wh0, a_wt0 + 64*c);
        ldsm4(wh1, a_wt1 + 64*c);
        unsigned bh0[4], bh1[4];
        ldsm4(bh0, bW2b_0 + 32*c);  ldsm4(bh1, bW2b_1 + 32*c);
        mma_2t(acc2, 0, wh0, wh1, bh0); mma_2t(acc2, 1, wh0, wh1, bh1);    // hi.hi
        {
            unsigned bl[4];
            ldsm4(bl, bW2b_0 + 128 + 32*c); mma_2t(acc2, 0, wh0, wh1, bl); // hi.lo
            ldsm4(bl, bW2b_1 + 128 + 32*c); mma_2t(acc2, 1, wh0, wh1, bl);
        }
        unsigned wl0[4], wl1[4];
        ldsm4(wl0, a_wt0 + 64*c + 32);
        ldsm4(wl1, a_wt1 + 64*c + 32);
        mma_2t(acc2, 0, wl0, wl1, bh0); mma_2t(acc2, 1, wl0, wl1, bh1);    // lo.hi
    }

    // ===== epilogue: +bx, direct fragment stores =====
    #pragma unroll
    for (int t = 0; t < 2; t++) {
        #pragma unroll
        for (int j = 0; j < 4; j++) {
            const int col = 32*sub + 8*j + 2*q;
            const float2 bx2 = *reinterpret_cast<const float2*>(sbx + col);
            const int r0 = rowbase + R0 + 16*t + rh;
            if (r0 < N)
                *reinterpret_cast<float2*>(gout + (size_t)r0 * 64 + col) =
                    make_float2(acc2[t][j][0] + bx2.x, acc2[t][j][1] + bx2.y);
            if (r0 + 8 < N)
                *reinterpret_cast<float2*>(gout + (size_t)(r0 + 8) * 64 + col) =
                    make_float2(acc2[t][j][2] + bx2.x, acc2[t][j][3] + bx2.y);
        }
    }
    #undef SPILL
    #undef PBAR
}

extern "C" void kernel_launch(void* const* d_in, const int* in_sizes, int n_in,
                              void* d_out, int out_size) {
    (void)n_in; (void)out_size;
    const float* x   = (const float*)d_in[0];
    const float* u   = (const float*)d_in[1];
    const float* A   = (const float*)d_in[2];
    const float* B1  = (const float*)d_in[3];
    const float* B2  = (const float*)d_in[4];
    const float* C1  = (const float*)d_in[5];
    const float* D11 = (const float*)d_in[6];
    const float* D12 = (const float*)d_in[7];
    const float* bv  = (const float*)d_in[8];
    const float* bx  = (const float*)d_in[9];
    float* out = (float*)d_out;

    const int N = in_sizes[0] / 64;                     // 262144
    const int grid = (N + MROWS - 1) / MROWS;           // 1024

    renl2_prep_kernel<<<8, 128>>>(A, B1, B2, C1, D11, D12);

    cudaFuncSetAttribute(renl2_hmma_kernel,
                         cudaFuncAttributeMaxDynamicSharedMemorySize,
                         SMEM_BYTES);
    renl2_hmma_kernel<<<grid, NTHREADS, SMEM_BYTES>>>(
        x, u, D11, bv, bx, out, N);
}

// round 14
// speedup vs baseline: 1.1027x; 1.1027x over previous
#include <cuda_runtime.h>
#include <cuda_bf16.h>
#include <cstdint>

#define NTHREADS 512
#define MROWS    256
#define SA 336            // act / W1 / W2a row stride in BYTES (168 bf16)
#define SW 272            // stage(f32x68) / wt / W2B / D11B row stride in BYTES

// ---------------- SMEM byte layout ----------------
#define OFF_W1    0        // bf16 [64 x 168]: C1_hi D12_hi | C1_lo D12_lo
#define OFF_W2A   21504    // bf16 [64 x 168]: A_hi  B2_hi  | A_lo  B2_lo
#define OFF_W2B   43008    // bf16 [64 x 136]: B1_hi | B1_lo
#define OFF_D11B  60416    // bf16 [48 x 136]: D11 rows 16..63, hi | lo
#define OFF_BV    73472    // f32 [64]
#define OFF_BX    73728    // f32 [64]
#define OFF_ACT   73984    // bf16 [256 x 168]: x_hi | u_hi | x_lo | u_lo
#define OFF_S     160000   // ALIASED: stage f32[256 x 68] / wt bf16 [hi_b|lo_b] at byte 64b
#define SMEM_BYTES 229632

__device__ __align__(16) unsigned char gW1s  [21504];
__device__ __align__(16) unsigned char gW2As [21504];
__device__ __align__(16) unsigned char gW2Bs [17408];
__device__ __align__(16) unsigned char gD11Bs[13056];

__device__ __forceinline__ uint32_t smem_u32(const void* p) {
    uint32_t a;
    asm("{ .reg .u64 t; cvta.to.shared.u64 t, %1; cvt.u32.u64 %0, t; }" : "=r"(a) : "l"(p));
    return a;
}
__device__ __forceinline__ void ldsm4(unsigned r[4], uint32_t addr) {
    asm volatile("ldmatrix.sync.aligned.m8n8.x4.shared.b16 {%0,%1,%2,%3}, [%4];"
        : "=r"(r[0]), "=r"(r[1]), "=r"(r[2]), "=r"(r[3]) : "r"(addr));
}
__device__ __forceinline__ void mma16816(float* d, const unsigned* a, unsigned b0, unsigned b1) {
    asm volatile("mma.sync.aligned.m16n8k16.row.col.f32.bf16.bf16.f32 "
        "{%0,%1,%2,%3},{%4,%5,%6,%7},{%8,%9},{%0,%1,%2,%3};"
        : "+f"(d[0]), "+f"(d[1]), "+f"(d[2]), "+f"(d[3])
        : "r"(a[0]), "r"(a[1]), "r"(a[2]), "r"(a[3]), "r"(b0), "r"(b1));
}
__device__ __forceinline__ void split2(float a, float b, unsigned& hi, unsigned& lo) {
    const __nv_bfloat16 ha = __float2bfloat16_rn(a), hb = __float2bfloat16_rn(b);
    hi = (unsigned)(*reinterpret_cast<const unsigned short*>(&ha))
       | ((unsigned)(*reinterpret_cast<const unsigned short*>(&hb)) << 16);
    const __nv_bfloat162 t = __floats2bfloat162_rn(a - __bfloat162float(ha),
                                                   b - __bfloat162float(hb));
    lo = *reinterpret_cast<const unsigned*>(&t);
}
__device__ __forceinline__ void gemm_b8(float (*acc)[4], uint32_t blane, int strideB,
                                        int cb, const unsigned a[4]) {
    #pragma unroll
    for (int p = 0; p < 4; p++) {
        unsigned bf[4];
        ldsm4(bf, blane + p * 16 * strideB + 32 * cb);
        mma16816(acc[2*p + 0], a, bf[0], bf[2]);
        mma16816(acc[2*p + 1], a, bf[1], bf[3]);
    }
}

// ---------------- prep kernel (8 CTAs) ----------------
__global__ void __launch_bounds__(128)
renl2_prep_kernel(const float* __restrict__ gA,  const float* __restrict__ gB1,
                  const float* __restrict__ gB2, const float* __restrict__ gC1,
                  const float* __restrict__ gD11,const float* __restrict__ gD12)
{
    const int tid = blockIdx.x * 128 + threadIdx.x;
    #pragma unroll 1
    for (int idx = tid; idx < 64 * 40; idx += 1024) {
        const int n = idx / 40, k = (idx - n * 40) * 2;
        float v1a, v1b, v2a, v2b;
        if (k < 64) { v1a = gC1[n*64 + k]; v1b = gC1[n*64 + k + 1];
                      v2a = gA [n*64 + k]; v2b = gA [n*64 + k + 1]; }
        else        { v1a = gD12[n*16 + k - 64]; v1b = gD12[n*16 + k - 63];
                      v2a = gB2 [n*16 + k - 64]; v2b = gB2 [n*16 + k - 63]; }
        unsigned h1, l1, h2, l2;
        split2(v1a, v1b, h1, l1);
        split2(v2a, v2b, h2, l2);
        *reinterpret_cast<unsigned*>(gW1s  + n*SA + 2*k)       = h1;
        *reinterpret_cast<unsigned*>(gW1s  + n*SA + 160 + 2*k) = l1;
        *reinterpret_cast<unsigned*>(gW2As + n*SA + 2*k)       = h2;
        *reinterpret_cast<unsigned*>(gW2As + n*SA + 160 + 2*k) = l2;
    }
    #pragma unroll 1
    for (int idx = tid; idx < 64 * 32; idx += 1024) {
        const int n = idx >> 5, k = (idx & 31) * 2;
        unsigned h, l;
        split2(gB1[n*64 + k], gB1[n*64 + k + 1], h, l);
        *reinterpret_cast<unsigned*>(gW2Bs + n*SW + 2*k)       = h;
        *reinterpret_cast<unsigned*>(gW2Bs + n*SW + 128 + 2*k) = l;
    }
    #pragma unroll 1
    for (int idx = tid; idx < 48 * 32; idx += 1024) {
        const int nl = idx >> 5, k = (idx & 31) * 2, n = nl + 16;
        unsigned h, l;
        split2(gD11[n*64 + k], gD11[n*64 + k + 1], h, l);
        *reinterpret_cast<unsigned*>(gD11Bs + nl*SW + 2*k)       = h;
        *reinterpret_cast<unsigned*>(gD11Bs + nl*SW + 128 + 2*k) = l;
    }
}

// ---------------- main kernel ----------------
__global__ void __launch_bounds__(NTHREADS, 1)
renl2_hmma_kernel(const float* __restrict__ gx,  const float* __restrict__ gu,
                  const float* __restrict__ gD11,
                  const float* __restrict__ gbv, const float* __restrict__ gbx,
                  float* __restrict__ gout, int N)
{
    extern __shared__ char smem[];
    const uint32_t sbase = smem_u32(smem);
    const int tid  = threadIdx.x;
    const int lane = tid & 31;
    const int wid  = tid >> 5;
    const int rowbase = blockIdx.x * MROWS;

    float* stage = reinterpret_cast<float*>(smem + OFF_S);    // aliased with wt
    float* sbv   = reinterpret_cast<float*>(smem + OFF_BV);
    float* sbx   = reinterpret_cast<float*>(smem + OFF_BX);

    // ---------- prefetch own-warp act rows into registers (before barrier) ----------
    // Warp wid owns act rows 16*wid..+15. Lane covers row 16*wid + (lane>>1),
    // x cols half*32..+31 (8 float4), u cols half*8..+7 (2 float4).
    const int arow  = 16*wid + (lane >> 1);
    const int ahalf = lane & 1;
    float4 xr[8], ur[2];
    {
        const bool ok = (rowbase + arow) < N;
        const float4* gx4 = reinterpret_cast<const float4*>(gx) + (size_t)(rowbase + arow) * 16 + ahalf * 8;
        const float4* gu4 = reinterpret_cast<const float4*>(gu) + (size_t)(rowbase + arow) * 4  + ahalf * 2;
        #pragma unroll
        for (int i = 0; i < 8; i++) xr[i] = ok ? gx4[i] : make_float4(0,0,0,0);
        ur[0] = ok ? gu4[0] : make_float4(0,0,0,0);
        ur[1] = ok ? gu4[1] : make_float4(0,0,0,0);
    }

    // ---------- copy pre-split weights + biases ----------
    {
        const uint4* s1 = reinterpret_cast<const uint4*>(gW1s);
        const uint4* s2 = reinterpret_cast<const uint4*>(gW2As);
        uint4* d1 = reinterpret_cast<uint4*>(smem + OFF_W1);
        uint4* d2 = reinterpret_cast<uint4*>(smem + OFF_W2A);
        #pragma unroll 1
        for (int i = tid; i < 21504/16; i += NTHREADS) { d1[i] = s1[i]; d2[i] = s2[i]; }
        const uint4* s3 = reinterpret_cast<const uint4*>(gW2Bs);
        uint4* d3 = reinterpret_cast<uint4*>(smem + OFF_W2B);
        #pragma unroll 1
        for (int i = tid; i < 17408/16; i += NTHREADS) d3[i] = s3[i];
        const uint4* s4 = reinterpret_cast<const uint4*>(gD11Bs);
        uint4* d4 = reinterpret_cast<uint4*>(smem + OFF_D11B);
        #pragma unroll 1
        for (int i = tid; i < 13056/16; i += NTHREADS) d4[i] = s4[i];
        if (tid >= 64 && tid < 128)  sbv[tid - 64]  = gbv[tid - 64];
        if (tid >= 128 && tid < 192) sbx[tid - 128] = gbx[tid - 128];
    }
    __syncthreads();   // ONLY block-wide barrier (weights + biases visible)

    // ---------- stage own act rows (warp-local, hi/lo split) ----------
    {
        char* rp = smem + OFF_ACT + arow * SA;
        #pragma unroll
        for (int i = 0; i < 8; i++) {
            const int q0 = ahalf * 8 + i;
            unsigned h0, l0, h1, l1;
            split2(xr[i].x, xr[i].y, h0, l0);
            split2(xr[i].z, xr[i].w, h1, l1);
            *reinterpret_cast<uint2*>(rp + 8*q0)       = make_uint2(h0, h1);
            *reinterpret_cast<uint2*>(rp + 160 + 8*q0) = make_uint2(l0, l1);
        }
        #pragma unroll
        for (int j = 0; j < 2; j++) {
            const int q0 = ahalf * 2 + j;
            unsigned h0, l0, h1, l1;
            split2(ur[j].x, ur[j].y, h0, l0);
            split2(ur[j].z, ur[j].w, h1, l1);
            *reinterpret_cast<uint2*>(rp + 128 + 8*q0) = make_uint2(h0, h1);
            *reinterpret_cast<uint2*>(rp + 288 + 8*q0) = make_uint2(l0, l1);
        }
    }
    __syncwarp();

    // ---------- per-warp pipeline (warp owns rows 16*wid..+15) ----------
    const uint32_t a_act  = sbase + OFF_ACT  + (16*wid + (lane & 15)) * SA + 16 * (lane >> 4);
    const uint32_t a_wt   = sbase + OFF_S    + (16*wid + (lane & 15)) * SW + 16 * (lane >> 4);
    const uint32_t b_w1   = sbase + OFF_W1   + (lane & 15) * SA + 16 * (lane >> 4);
    const uint32_t b_w2a  = sbase + OFF_W2A  + (lane & 15) * SA + 16 * (lane >> 4);
    const uint32_t b_w2b  = sbase + OFF_W2B  + (lane & 15) * SW + 16 * (lane >> 4);
    const uint32_t b_d11  = sbase + OFF_D11B + (lane & 15) * SW + 16 * (lane >> 4);

    const int q  = lane & 3;
    const int rh = lane >> 2;

    // ===== GEMM1: base = [act] x W1^T ; keep acc live, spill only block 0 =====
    float acc[8][4] = {};
    #pragma unroll
    for (int c = 0; c < 5; c++) {
        unsigned ah[4], al[4];
        ldsm4(ah, a_act + 32 * c);
        gemm_b8(acc, b_w1, SA, c,     ah);      // hi . hi
        gemm_b8(acc, b_w1, SA, 5 + c, ah);      // hi . lo
        ldsm4(al, a_act + 32 * (5 + c));
        gemm_b8(acc, b_w1, SA, c,     al);      // lo . hi
    }
    #pragma unroll
    for (int n = 0; n < 2; n++) {               // only block-0 cols to stage
        const int c0 = 8*n + 2*q;
        *reinterpret_cast<float2*>(stage + (16*wid + rh    ) * 68 + c0) = make_float2(acc[n][0], acc[n][1]);
        *reinterpret_cast<float2*>(stage + (16*wid + rh + 8) * 68 + c0) = make_float2(acc[n][2], acc[n][3]);
    }
    __syncwarp();

    // ===== blocked triangular solve with ReLU =====
    #pragma unroll
    for (int b = 0; b < 4; b++) {
        // --- diagonal 16x16 serial solve (lanes 0-15, one sample each) ---
        if (lane < 16) {
            const int row = 16*wid + lane;
            float wv[16];
            const float4* srow = reinterpret_cast<const float4*>(stage + row * 68 + 16*b);
            const float4* bvp  = reinterpret_cast<const float4*>(sbv + 16*b);
            #pragma unroll
            for (int g = 0; g < 4; g++) {
                const float4 s = srow[g], v = bvp[g];
                wv[4*g+0] = s.x + v.x; wv[4*g+1] = s.y + v.y;
                wv[4*g+2] = s.z + v.z; wv[4*g+3] = s.w + v.w;
            }
            wv[0] = fmaxf(wv[0], 0.0f);
            #pragma unroll
            for (int il = 1; il < 16; il++) {
                const float4* dptr = reinterpret_cast<const float4*>(gD11 + (16*b + il) * 64 + 16*b);
                float a0 = wv[il], a1 = 0.0f, a2 = 0.0f, a3 = 0.0f;
                const int ng = (il + 3) >> 2;
                #pragma unroll
                for (int g = 0; g < 4; g++) {
                    if (g >= ng) break;                  // strict-lower zeros pad tail
                    const float4 d = dptr[g];
                    a0 = fmaf(d.x, wv[4*g+0], a0);
                    a1 = fmaf(d.y, wv[4*g+1], a1);
                    a2 = fmaf(d.z, wv[4*g+2], a2);
                    a3 = fmaf(d.w, wv[4*g+3], a3);
                }
                wv[il] = fmaxf((a0 + a1) + (a2 + a3), 0.0f);
            }
            // write w_b as bf16 [hi_b | lo_b] over the stage bytes just consumed
            char* wtp = smem + OFF_S + row * SW + 64*b;
            unsigned hp[8], lp[8];
            #pragma unroll
            for (int t = 0; t < 8; t++) split2(wv[2*t], wv[2*t+1], hp[t], lp[t]);
            *reinterpret_cast<uint4*>(wtp)      = make_uint4(hp[0], hp[1], hp[2], hp[3]);
            *reinterpret_cast<uint4*>(wtp + 16) = make_uint4(hp[4], hp[5], hp[6], hp[7]);
            *reinterpret_cast<uint4*>(wtp + 32) = make_uint4(lp[0], lp[1], lp[2], lp[3]);
            *reinterpret_cast<uint4*>(wtp + 48) = make_uint4(lp[4], lp[5], lp[6], lp[7]);
        }
        __syncwarp();

        // --- HMMA update of remaining cols, then spill next block to stage ---
        if (b < 3) {
            unsigned ahi[4], alo[4];
            ldsm4(ahi, a_wt + 64*b);
            ldsm4(alo, a_wt + 64*b + 32);
            #pragma unroll
            for (int p = 1; p < 4; p++) {
                if (p <= b) continue;             // compile-time trimmed
                unsigned bh[4], bl[4];
                const uint32_t bb = b_d11 + (p - 1) * 16 * SW;
                ldsm4(bh, bb + 32*b);
                ldsm4(bl, bb + 128 + 32*b);
                mma16816(acc[2*p    ], ahi, bh[0], bh[2]);
                mma16816(acc[2*p + 1], ahi, bh[1], bh[3]);
                mma16816(acc[2*p    ], alo, bh[0], bh[2]);
                mma16816(acc[2*p + 1], alo, bh[1], bh[3]);
                mma16816(acc[2*p    ], ahi, bl[0], bl[2]);
                mma16816(acc[2*p + 1], ahi, bl[1], bl[3]);
            }
            #pragma unroll
            for (int n = 2*(b+1); n <= 2*(b+1) + 1; n++) {
                const int c0 = 8*n + 2*q;
                *reinterpret_cast<float2*>(stage + (16*wid + rh    ) * 68 + c0) = make_float2(acc[n][0], acc[n][1]);
                *reinterpret_cast<float2*>(stage + (16*wid + rh + 8) * 68 + c0) = make_float2(acc[n][2], acc[n][3]);
            }
            __syncwarp();
        }
    }
    __syncwarp();

    // ===== GEMM2: out = [act] x W2a^T + [w] x B1^T =====
    float acc2[8][4] = {};
    #pragma unroll
    for (int c = 0; c < 5; c++) {
        unsigned ah[4], al[4];
        ldsm4(ah, a_act + 32 * c);
        gemm_b8(acc2, b_w2a, SA, c,     ah);
        gemm_b8(acc2, b_w2a, SA, 5 + c, ah);
        ldsm4(al, a_act + 32 * (5 + c));
        gemm_b8(acc2, b_w2a, SA, c,     al);
    }
    #pragma unroll
    for (int c = 0; c < 4; c++) {
        unsigned ah[4], al[4];
        ldsm4(ah, a_wt + 64*c);             // w hi chunk c (interleaved layout)
        gemm_b8(acc2, b_w2b, SW, c,     ah);
        gemm_b8(acc2, b_w2b, SW, 4 + c, ah);
        ldsm4(al, a_wt + 64*c + 32);        // w lo chunk c
        gemm_b8(acc2, b_w2b, SW, c,     al);
    }

    // ===== epilogue: +bx in registers, direct fragment stores =====
    #pragma unroll
    for (int n = 0; n < 8; n++) {
        const int col = 8*n + 2*q;
        const float2 bx2 = *reinterpret_cast<const float2*>(sbx + col);
        const int r0 = rowbase + 16*wid + rh;
        if (r0 < N)
            *reinterpret_cast<float2*>(gout + (size_t)r0 * 64 + col) =
                make_float2(acc2[n][0] + bx2.x, acc2[n][1] + bx2.y);
        if (r0 + 8 < N)
            *reinterpret_cast<float2*>(gout + (size_t)(r0 + 8) * 64 + col) =
                make_float2(acc2[n][2] + bx2.x, acc2[n][3] + bx2.y);
    }
}

extern "C" void kernel_launch(void* const* d_in, const int* in_sizes, int n_in,
                              void* d_out, int out_size) {
    (void)n_in; (void)out_size;
    const float* x   = (const float*)d_in[0];
    const float* u   = (const float*)d_in[1];
    const float* A   = (const float*)d_in[2];
    const float* B1  = (const float*)d_in[3];
    const float* B2  = (const float*)d_in[4];
    const float* C1  = (const float*)d_in[5];
    const float* D11 = (const float*)d_in[6];
    const float* D12 = (const float*)d_in[7];
    const float* bv  = (const float*)d_in[8];
    const float* bx  = (const float*)d_in[9];
    float* out = (float*)d_out;

    const int N = in_sizes[0] / 64;                     // 262144
    const int grid = (N + MROWS - 1) / MROWS;           // 1024

    renl2_prep_kernel<<<8, 128>>>(A, B1, B2, C1, D11, D12);

    cudaFuncSetAttribute(renl2_hmma_kernel,
                         cudaFuncAttributeMaxDynamicSharedMemorySize,
                         SMEM_BYTES);
    renl2_hmma_kernel<<<grid, NTHREADS, SMEM_BYTES>>>(
        x, u, D11, bv, bx, out, N);
}

// round 15
// speedup vs baseline: 1.1124x; 1.0088x over previous
#include <cuda_runtime.h>
#include <cuda_bf16.h>
#include <cstdint>

#define NTHREADS 512
#define MROWS    256
#define SA 336            // act / W1 / W2a row stride in BYTES (168 bf16)
#define SW 272            // stage(f32x68) / wt / W2B / D11B row stride in BYTES

// ---------------- SMEM byte layout ----------------
#define OFF_W1    0        // bf16 [64 x 168]: C1_hi D12_hi | C1_lo D12_lo
#define OFF_W2A   21504    // bf16 [64 x 168]: A_hi  B2_hi  | A_lo  B2_lo
#define OFF_W2B   43008    // bf16 [64 x 136]: B1_hi | B1_lo
#define OFF_D11B  60416    // bf16 [48 x 136]: D11 rows 16..63, hi | lo
#define OFF_BV    73472    // f32 [64]
#define OFF_BX    73728    // f32 [64]
#define OFF_ACT   73984    // bf16 [256 x 168]: x_hi | u_hi | x_lo | u_lo
#define OFF_S     160000   // ALIASED: stage f32[256 x 68] / wt bf16 [hi_b|lo_b] at byte 64b
#define SMEM_BYTES 229632

__device__ __align__(16) unsigned char gW1s  [21504];
__device__ __align__(16) unsigned char gW2As [21504];
__device__ __align__(16) unsigned char gW2Bs [17408];
__device__ __align__(16) unsigned char gD11Bs[13056];

__device__ __forceinline__ uint32_t smem_u32(const void* p) {
    uint32_t a;
    asm("{ .reg .u64 t; cvta.to.shared.u64 t, %1; cvt.u32.u64 %0, t; }" : "=r"(a) : "l"(p));
    return a;
}
__device__ __forceinline__ void ldsm4(unsigned r[4], uint32_t addr) {
    asm volatile("ldmatrix.sync.aligned.m8n8.x4.shared.b16 {%0,%1,%2,%3}, [%4];"
        : "=r"(r[0]), "=r"(r[1]), "=r"(r[2]), "=r"(r[3]) : "r"(addr));
}
__device__ __forceinline__ void mma16816(float* d, const unsigned* a, unsigned b0, unsigned b1) {
    asm volatile("mma.sync.aligned.m16n8k16.row.col.f32.bf16.bf16.f32 "
        "{%0,%1,%2,%3},{%4,%5,%6,%7},{%8,%9},{%0,%1,%2,%3};"
        : "+f"(d[0]), "+f"(d[1]), "+f"(d[2]), "+f"(d[3])
        : "r"(a[0]), "r"(a[1]), "r"(a[2]), "r"(a[3]), "r"(b0), "r"(b1));
}
__device__ __forceinline__ void split2(float a, float b, unsigned& hi, unsigned& lo) {
    const __nv_bfloat16 ha = __float2bfloat16_rn(a), hb = __float2bfloat16_rn(b);
    hi = (unsigned)(*reinterpret_cast<const unsigned short*>(&ha))
       | ((unsigned)(*reinterpret_cast<const unsigned short*>(&hb)) << 16);
    const __nv_bfloat162 t = __floats2bfloat162_rn(a - __bfloat162float(ha),
                                                   b - __bfloat162float(hb));
    lo = *reinterpret_cast<const unsigned*>(&t);
}
// one chunk of a 3-product split GEMM with B-fragment register reuse:
//   acc += ah x Bhi  (hi.hi), al x Bhi (lo.hi), ah x Blo (hi.lo)
// b_hi / b_lo: lane base addresses of hi and lo chunks of the weight tile.
__device__ __forceinline__ void gemm_chunk_reuse(float (*acc)[4], uint32_t b_hi, uint32_t b_lo,
                                                 int strideB, const unsigned ah[4], const unsigned al[4]) {
    #pragma unroll
    for (int p = 0; p < 4; p++) {
        unsigned bh[4];
        ldsm4(bh, b_hi + p * 16 * strideB);
        mma16816(acc[2*p + 0], ah, bh[0], bh[2]);
        mma16816(acc[2*p + 1], ah, bh[1], bh[3]);
        mma16816(acc[2*p + 0], al, bh[0], bh[2]);
        mma16816(acc[2*p + 1], al, bh[1], bh[3]);
        unsigned bl[4];
        ldsm4(bl, b_lo + p * 16 * strideB);
        mma16816(acc[2*p + 0], ah, bl[0], bl[2]);
        mma16816(acc[2*p + 1], ah, bl[1], bl[3]);
    }
}

// ---------------- prep kernel (8 CTAs) ----------------
__global__ void __launch_bounds__(128)
renl2_prep_kernel(const float* __restrict__ gA,  const float* __restrict__ gB1,
                  const float* __restrict__ gB2, const float* __restrict__ gC1,
                  const float* __restrict__ gD11,const float* __restrict__ gD12)
{
    const int tid = blockIdx.x * 128 + threadIdx.x;
    #pragma unroll 1
    for (int idx = tid; idx < 64 * 40; idx += 1024) {
        const int n = idx / 40, k = (idx - n * 40) * 2;
        float v1a, v1b, v2a, v2b;
        if (k < 64) { v1a = gC1[n*64 + k]; v1b = gC1[n*64 + k + 1];
                      v2a = gA [n*64 + k]; v2b = gA [n*64 + k + 1]; }
        else        { v1a = gD12[n*16 + k - 64]; v1b = gD12[n*16 + k - 63];
                      v2a = gB2 [n*16 + k - 64]; v2b = gB2 [n*16 + k - 63]; }
        unsigned h1, l1, h2, l2;
        split2(v1a, v1b, h1, l1);
        split2(v2a, v2b, h2, l2);
        *reinterpret_cast<unsigned*>(gW1s  + n*SA + 2*k)       = h1;
        *reinterpret_cast<unsigned*>(gW1s  + n*SA + 160 + 2*k) = l1;
        *reinterpret_cast<unsigned*>(gW2As + n*SA + 2*k)       = h2;
        *reinterpret_cast<unsigned*>(gW2As + n*SA + 160 + 2*k) = l2;
    }
    #pragma unroll 1
    for (int idx = tid; idx < 64 * 32; idx += 1024) {
        const int n = idx >> 5, k = (idx & 31) * 2;
        unsigned h, l;
        split2(gB1[n*64 + k], gB1[n*64 + k + 1], h, l);
        *reinterpret_cast<unsigned*>(gW2Bs + n*SW + 2*k)       = h;
        *reinterpret_cast<unsigned*>(gW2Bs + n*SW + 128 + 2*k) = l;
    }
    #pragma unroll 1
    for (int idx = tid; idx < 48 * 32; idx += 1024) {
        const int nl = idx >> 5, k = (idx & 31) * 2, n = nl + 16;
        unsigned h, l;
        split2(gD11[n*64 + k], gD11[n*64 + k + 1], h, l);
        *reinterpret_cast<unsigned*>(gD11Bs + nl*SW + 2*k)       = h;
        *reinterpret_cast<unsigned*>(gD11Bs + nl*SW + 128 + 2*k) = l;
    }
}

// ---------------- main kernel ----------------
__global__ void __launch_bounds__(NTHREADS, 1)
renl2_hmma_kernel(const float* __restrict__ gx,  const float* __restrict__ gu,
                  const float* __restrict__ gD11,
                  const float* __restrict__ gbv, const float* __restrict__ gbx,
                  float* __restrict__ gout, int N)
{
    extern __shared__ char smem[];
    const uint32_t sbase = smem_u32(smem);
    const int tid  = threadIdx.x;
    const int lane = tid & 31;
    const int wid  = tid >> 5;
    const int rowbase = blockIdx.x * MROWS;

    float* stage = reinterpret_cast<float*>(smem + OFF_S);    // aliased with wt
    float* sbv   = reinterpret_cast<float*>(smem + OFF_BV);
    float* sbx   = reinterpret_cast<float*>(smem + OFF_BX);

    // ---------- prefetch own-warp act rows into registers (before barrier) ----------
    const int arow  = 16*wid + (lane >> 1);
    const int ahalf = lane & 1;
    float4 xr[8], ur[2];
    {
        const bool ok = (rowbase + arow) < N;
        const float4* gx4 = reinterpret_cast<const float4*>(gx) + (size_t)(rowbase + arow) * 16 + ahalf * 8;
        const float4* gu4 = reinterpret_cast<const float4*>(gu) + (size_t)(rowbase + arow) * 4  + ahalf * 2;
        #pragma unroll
        for (int i = 0; i < 8; i++) xr[i] = ok ? gx4[i] : make_float4(0,0,0,0);
        ur[0] = ok ? gu4[0] : make_float4(0,0,0,0);
        ur[1] = ok ? gu4[1] : make_float4(0,0,0,0);
    }

    // ---------- copy pre-split weights + biases ----------
    {
        const uint4* s1 = reinterpret_cast<const uint4*>(gW1s);
        const uint4* s2 = reinterpret_cast<const uint4*>(gW2As);
        uint4* d1 = reinterpret_cast<uint4*>(smem + OFF_W1);
        uint4* d2 = reinterpret_cast<uint4*>(smem + OFF_W2A);
        #pragma unroll 1
        for (int i = tid; i < 21504/16; i += NTHREADS) { d1[i] = s1[i]; d2[i] = s2[i]; }
        const uint4* s3 = reinterpret_cast<const uint4*>(gW2Bs);
        uint4* d3 = reinterpret_cast<uint4*>(smem + OFF_W2B);
        #pragma unroll 1
        for (int i = tid; i < 17408/16; i += NTHREADS) d3[i] = s3[i];
        const uint4* s4 = reinterpret_cast<const uint4*>(gD11Bs);
        uint4* d4 = reinterpret_cast<uint4*>(smem + OFF_D11B);
        #pragma unroll 1
        for (int i = tid; i < 13056/16; i += NTHREADS) d4[i] = s4[i];
        if (tid >= 64 && tid < 128)  sbv[tid - 64]  = gbv[tid - 64];
        if (tid >= 128 && tid < 192) sbx[tid - 128] = gbx[tid - 128];
    }
    __syncthreads();   // ONLY block-wide barrier

    // ---------- stage own act rows (warp-local, hi/lo split) ----------
    {
        char* rp = smem + OFF_ACT + arow * SA;
        #pragma unroll
        for (int i = 0; i < 8; i++) {
            const int q0 = ahalf * 8 + i;
            unsigned h0, l0, h1, l1;
            split2(xr[i].x, xr[i].y, h0, l0);
            split2(xr[i].z, xr[i].w, h1, l1);
            *reinterpret_cast<uint2*>(rp + 8*q0)       = make_uint2(h0, h1);
            *reinterpret_cast<uint2*>(rp + 160 + 8*q0) = make_uint2(l0, l1);
        }
        #pragma unroll
        for (int j = 0; j < 2; j++) {
            const int q0 = ahalf * 2 + j;
            unsigned h0, l0, h1, l1;
            split2(ur[j].x, ur[j].y, h0, l0);
            split2(ur[j].z, ur[j].w, h1, l1);
            *reinterpret_cast<uint2*>(rp + 128 + 8*q0) = make_uint2(h0, h1);
            *reinterpret_cast<uint2*>(rp + 288 + 8*q0) = make_uint2(l0, l1);
        }
    }
    __syncwarp();

    // ---------- per-warp pipeline (warp owns rows 16*wid..+15) ----------
    const uint32_t a_act  = sbase + OFF_ACT  + (16*wid + (lane & 15)) * SA + 16 * (lane >> 4);
    const uint32_t a_wt   = sbase + OFF_S    + (16*wid + (lane & 15)) * SW + 16 * (lane >> 4);
    const uint32_t b_w1   = sbase + OFF_W1   + (lane & 15) * SA + 16 * (lane >> 4);
    const uint32_t b_w2a  = sbase + OFF_W2A  + (lane & 15) * SA + 16 * (lane >> 4);
    const uint32_t b_w2b  = sbase + OFF_W2B  + (lane & 15) * SW + 16 * (lane >> 4);
    const uint32_t b_d11  = sbase + OFF_D11B + (lane & 15) * SW + 16 * (lane >> 4);

    const int q  = lane & 3;
    const int rh = lane >> 2;

    // ===== GEMM1: base = [act] x W1^T (B-frag reuse); spill only block 0 =====
    float acc[8][4] = {};
    #pragma unroll
    for (int c = 0; c < 5; c++) {
        unsigned ah[4], al[4];
        ldsm4(ah, a_act + 32 * c);
        ldsm4(al, a_act + 32 * (5 + c));
        gemm_chunk_reuse(acc, b_w1 + 32*c, b_w1 + 32*(5+c), SA, ah, al);
    }
    #pragma unroll
    for (int n = 0; n < 2; n++) {               // only block-0 cols to stage
        const int c0 = 8*n + 2*q;
        *reinterpret_cast<float2*>(stage + (16*wid + rh    ) * 68 + c0) = make_float2(acc[n][0], acc[n][1]);
        *reinterpret_cast<float2*>(stage + (16*wid + rh + 8) * 68 + c0) = make_float2(acc[n][2], acc[n][3]);
    }
    __syncwarp();

    // ===== blocked triangular solve with ReLU =====
    #pragma unroll
    for (int b = 0; b < 4; b++) {
        // --- diagonal 16x16 serial solve (lanes 0-15, one sample each) ---
        if (lane < 16) {
            const int row = 16*wid + lane;
            float wv[16];
            const float4* srow = reinterpret_cast<const float4*>(stage + row * 68 + 16*b);
            const float4* bvp  = reinterpret_cast<const float4*>(sbv + 16*b);
            #pragma unroll
            for (int g = 0; g < 4; g++) {
                const float4 s = srow[g], v = bvp[g];
                wv[4*g+0] = s.x + v.x; wv[4*g+1] = s.y + v.y;
                wv[4*g+2] = s.z + v.z; wv[4*g+3] = s.w + v.w;
            }
            wv[0] = fmaxf(wv[0], 0.0f);
            #pragma unroll
            for (int il = 1; il < 16; il++) {
                const float4* dptr = reinterpret_cast<const float4*>(gD11 + (16*b + il) * 64 + 16*b);
                float a0 = wv[il], a1 = 0.0f, a2 = 0.0f, a3 = 0.0f;
                const int ng = (il + 3) >> 2;
                #pragma unroll
                for (int g = 0; g < 4; g++) {
                    if (g >= ng) break;                  // strict-lower zeros pad tail
                    const float4 d = dptr[g];
                    a0 = fmaf(d.x, wv[4*g+0], a0);
                    a1 = fmaf(d.y, wv[4*g+1], a1);
                    a2 = fmaf(d.z, wv[4*g+2], a2);
                    a3 = fmaf(d.w, wv[4*g+3], a3);
                }
                wv[il] = fmaxf((a0 + a1) + (a2 + a3), 0.0f);
            }
            // write w_b as bf16 [hi_b | lo_b] over the stage bytes just consumed
            char* wtp = smem + OFF_S + row * SW + 64*b;
            unsigned hp[8], lp[8];
            #pragma unroll
            for (int t = 0; t < 8; t++) split2(wv[2*t], wv[2*t+1], hp[t], lp[t]);
            *reinterpret_cast<uint4*>(wtp)      = make_uint4(hp[0], hp[1], hp[2], hp[3]);
            *reinterpret_cast<uint4*>(wtp + 16) = make_uint4(hp[4], hp[5], hp[6], hp[7]);
            *reinterpret_cast<uint4*>(wtp + 32) = make_uint4(lp[0], lp[1], lp[2], lp[3]);
            *reinterpret_cast<uint4*>(wtp + 48) = make_uint4(lp[4], lp[5], lp[6], lp[7]);
        }
        __syncwarp();

        // --- HMMA update of remaining cols, then spill next block to stage ---
        if (b < 3) {
            unsigned ahi[4], alo[4];
            ldsm4(ahi, a_wt + 64*b);
            ldsm4(alo, a_wt + 64*b + 32);
            #pragma unroll
            for (int p = 1; p < 4; p++) {
                if (p <= b) continue;             // compile-time trimmed
                unsigned bh[4], bl[4];
                const uint32_t bb = b_d11 + (p - 1) * 16 * SW;
                ldsm4(bh, bb + 32*b);
                mma16816(acc[2*p    ], ahi, bh[0], bh[2]);
                mma16816(acc[2*p + 1], ahi, bh[1], bh[3]);
                mma16816(acc[2*p    ], alo, bh[0], bh[2]);
                mma16816(acc[2*p + 1], alo, bh[1], bh[3]);
                ldsm4(bl, bb + 128 + 32*b);
                mma16816(acc[2*p    ], ahi, bl[0], bl[2]);
                mma16816(acc[2*p + 1], ahi, bl[1], bl[3]);
            }
            #pragma unroll
            for (int n = 2*(b+1); n <= 2*(b+1) + 1; n++) {
                const int c0 = 8*n + 2*q;
                *reinterpret_cast<float2*>(stage + (16*wid + rh    ) * 68 + c0) = make_float2(acc[n][0], acc[n][1]);
                *reinterpret_cast<float2*>(stage + (16*wid + rh + 8) * 68 + c0) = make_float2(acc[n][2], acc[n][3]);
            }
            __syncwarp();
        }
    }
    __syncwarp();

    // ===== GEMM2: out = [act] x W2a^T + [w] x B1^T (B-frag reuse) =====
    float acc2[8][4] = {};
    #pragma unroll
    for (int c = 0; c < 5; c++) {
        unsigned ah[4], al[4];
        ldsm4(ah, a_act + 32 * c);
        ldsm4(al, a_act + 32 * (5 + c));
        gemm_chunk_reuse(acc2, b_w2a + 32*c, b_w2a + 32*(5+c), SA, ah, al);
    }
    #pragma unroll
    for (int c = 0; c < 4; c++) {
        unsigned wh[4], wl[4];
        ldsm4(wh, a_wt + 64*c);             // w hi chunk c (interleaved layout)
        ldsm4(wl, a_wt + 64*c + 32);        // w lo chunk c
        gemm_chunk_reuse(acc2, b_w2b + 32*c, b_w2b + 128 + 32*c, SW, wh, wl);
    }

    // ===== epilogue: +bx in registers, direct fragment stores =====
    #pragma unroll
    for (int n = 0; n < 8; n++) {
        const int col = 8*n + 2*q;
        const float2 bx2 = *reinterpret_cast<const float2*>(sbx + col);
        const int r0 = rowbase + 16*wid + rh;
        if (r0 < N)
            *reinterpret_cast<float2*>(gout + (size_t)r0 * 64 + col) =
                make_float2(acc2[n][0] + bx2.x, acc2[n][1] + bx2.y);
        if (r0 + 8 < N)
            *reinterpret_cast<float2*>(gout + (size_t)(r0 + 8) * 64 + col) =
                make_float2(acc2[n][2] + bx2.x, acc2[n][3] + bx2.y);
    }
}

extern "C" void kernel_launch(void* const* d_in, const int* in_sizes, int n_in,
                              void* d_out, int out_size) {
    (void)n_in; (void)out_size;
    const float* x   = (const float*)d_in[0];
    const float* u   = (const float*)d_in[1];
    const float* A   = (const float*)d_in[2];
    const float* B1  = (const float*)d_in[3];
    const float* B2  = (const float*)d_in[4];
    const float* C1  = (const float*)d_in[5];
    const float* D11 = (const float*)d_in[6];
    const float* D12 = (const float*)d_in[7];
    const float* bv  = (const float*)d_in[8];
    const float* bx  = (const float*)d_in[9];
    float* out = (float*)d_out;

    const int N = in_sizes[0] / 64;                     // 262144
    const int grid = (N + MROWS - 1) / MROWS;           // 1024

    renl2_prep_kernel<<<8, 128>>>(A, B1, B2, C1, D11, D12);

    cudaFuncSetAttribute(renl2_hmma_kernel,
                         cudaFuncAttributeMaxDynamicSharedMemorySize,
                         SMEM_BYTES);
    renl2_hmma_kernel<<<grid, NTHREADS, SMEM_BYTES>>>(
        x, u, D11, bv, bx, out, N);
}

// round 16
// speedup vs baseline: 1.2620x; 1.1345x over previous
#include <cuda_runtime.h>
#include <cuda_bf16.h>
#include <cstdint>

#define NTHREADS 512
#define MROWS    256
#define SA 336            // act / W1 / W2a row stride in BYTES (168 bf16)
#define SW 272            // stage(f32x68) / wt / W2B / D11B row stride in BYTES

// ---------------- SMEM byte layout ----------------
#define OFF_W1    0        // bf16 [64 x 168]: C1_hi D12_hi | C1_lo D12_lo
#define OFF_W2A   21504    // bf16 [64 x 168]: A_hi  B2_hi  | A_lo  B2_lo
#define OFF_W2B   43008    // bf16 [64 x 136]: B1_hi | B1_lo
#define OFF_D11B  60416    // bf16 [48 x 136]: D11 rows 16..63, hi | lo
#define OFF_BV    73472    // f32 [64]
#define OFF_BX    73728    // f32 [64]
#define OFF_ACT   73984    // bf16 [256 x 168]: x_hi | u_hi | x_lo | u_lo
#define OFF_S     160000   // ALIASED: stage f32[256 x 68] / wt bf16 [hi_b|lo_b] at byte 64b
#define SMEM_BYTES 229632

__device__ __align__(16) unsigned char gW1s  [21504];
__device__ __align__(16) unsigned char gW2As [21504];
__device__ __align__(16) unsigned char gW2Bs [17408];
__device__ __align__(16) unsigned char gD11Bs[13056];

__device__ __forceinline__ uint32_t smem_u32(const void* p) {
    uint32_t a;
    asm("{ .reg .u64 t; cvta.to.shared.u64 t, %1; cvt.u32.u64 %0, t; }" : "=r"(a) : "l"(p));
    return a;
}
__device__ __forceinline__ void ldsm4(unsigned r[4], uint32_t addr) {
    asm volatile("ldmatrix.sync.aligned.m8n8.x4.shared.b16 {%0,%1,%2,%3}, [%4];"
        : "=r"(r[0]), "=r"(r[1]), "=r"(r[2]), "=r"(r[3]) : "r"(addr));
}
__device__ __forceinline__ void mma16816(float* d, const unsigned* a, unsigned b0, unsigned b1) {
    asm volatile("mma.sync.aligned.m16n8k16.row.col.f32.bf16.bf16.f32 "
        "{%0,%1,%2,%3},{%4,%5,%6,%7},{%8,%9},{%0,%1,%2,%3};"
        : "+f"(d[0]), "+f"(d[1]), "+f"(d[2]), "+f"(d[3])
        : "r"(a[0]), "r"(a[1]), "r"(a[2]), "r"(a[3]), "r"(b0), "r"(b1));
}
__device__ __forceinline__ void split2(float a, float b, unsigned& hi, unsigned& lo) {
    const __nv_bfloat16 ha = __float2bfloat16_rn(a), hb = __float2bfloat16_rn(b);
    hi = (unsigned)(*reinterpret_cast<const unsigned short*>(&ha))
       | ((unsigned)(*reinterpret_cast<const unsigned short*>(&hb)) << 16);
    const __nv_bfloat162 t = __floats2bfloat162_rn(a - __bfloat162float(ha),
                                                   b - __bfloat162float(hb));
    lo = *reinterpret_cast<const unsigned*>(&t);
}
// one chunk of a 3-product split GEMM with B-fragment register reuse:
//   acc += ah x Bhi (hi.hi), al x Bhi (lo.hi), ah x Blo (hi.lo)
__device__ __forceinline__ void gemm_chunk_reuse(float (*acc)[4], uint32_t b_hi, uint32_t b_lo,
                                                 int strideB, const unsigned ah[4], const unsigned al[4]) {
    #pragma unroll
    for (int p = 0; p < 4; p++) {
        unsigned bh[4];
        ldsm4(bh, b_hi + p * 16 * strideB);
        mma16816(acc[2*p + 0], ah, bh[0], bh[2]);
        mma16816(acc[2*p + 1], ah, bh[1], bh[3]);
        mma16816(acc[2*p + 0], al, bh[0], bh[2]);
        mma16816(acc[2*p + 1], al, bh[1], bh[3]);
        unsigned bl[4];
        ldsm4(bl, b_lo + p * 16 * strideB);
        mma16816(acc[2*p + 0], ah, bl[0], bl[2]);
        mma16816(acc[2*p + 1], ah, bl[1], bl[3]);
    }
}

// ---------------- prep kernel (8 CTAs) ----------------
__global__ void __launch_bounds__(128)
renl2_prep_kernel(const float* __restrict__ gA,  const float* __restrict__ gB1,
                  const float* __restrict__ gB2, const float* __restrict__ gC1,
                  const float* __restrict__ gD11,const float* __restrict__ gD12)
{
    const int tid = blockIdx.x * 128 + threadIdx.x;
    #pragma unroll 1
    for (int idx = tid; idx < 64 * 40; idx += 1024) {
        const int n = idx / 40, k = (idx - n * 40) * 2;
        float v1a, v1b, v2a, v2b;
        if (k < 64) { v1a = gC1[n*64 + k]; v1b = gC1[n*64 + k + 1];
                      v2a = gA [n*64 + k]; v2b = gA [n*64 + k + 1]; }
        else        { v1a = gD12[n*16 + k - 64]; v1b = gD12[n*16 + k - 63];
                      v2a = gB2 [n*16 + k - 64]; v2b = gB2 [n*16 + k - 63]; }
        unsigned h1, l1, h2, l2;
        split2(v1a, v1b, h1, l1);
        split2(v2a, v2b, h2, l2);
        *reinterpret_cast<unsigned*>(gW1s  + n*SA + 2*k)       = h1;
        *reinterpret_cast<unsigned*>(gW1s  + n*SA + 160 + 2*k) = l1;
        *reinterpret_cast<unsigned*>(gW2As + n*SA + 2*k)       = h2;
        *reinterpret_cast<unsigned*>(gW2As + n*SA + 160 + 2*k) = l2;
    }
    #pragma unroll 1
    for (int idx = tid; idx < 64 * 32; idx += 1024) {
        const int n = idx >> 5, k = (idx & 31) * 2;
        unsigned h, l;
        split2(gB1[n*64 + k], gB1[n*64 + k + 1], h, l);
        *reinterpret_cast<unsigned*>(gW2Bs + n*SW + 2*k)       = h;
        *reinterpret_cast<unsigned*>(gW2Bs + n*SW + 128 + 2*k) = l;
    }
    #pragma unroll 1
    for (int idx = tid; idx < 48 * 32; idx += 1024) {
        const int nl = idx >> 5, k = (idx & 31) * 2, n = nl + 16;
        unsigned h, l;
        split2(gD11[n*64 + k], gD11[n*64 + k + 1], h, l);
        *reinterpret_cast<unsigned*>(gD11Bs + nl*SW + 2*k)       = h;
        *reinterpret_cast<unsigned*>(gD11Bs + nl*SW + 128 + 2*k) = l;
    }
}

// ---------------- main kernel: persistent CTAs over row-tiles ----------------
__global__ void __launch_bounds__(NTHREADS, 1)
renl2_hmma_kernel(const float* __restrict__ gx,  const float* __restrict__ gu,
                  const float* __restrict__ gD11,
                  const float* __restrict__ gbv, const float* __restrict__ gbx,
                  float* __restrict__ gout, int N, int nTiles)
{
    extern __shared__ char smem[];
    const uint32_t sbase = smem_u32(smem);
    const int tid  = threadIdx.x;
    const int lane = tid & 31;
    const int wid  = tid >> 5;

    float* stage = reinterpret_cast<float*>(smem + OFF_S);    // aliased with wt
    float* sbv   = reinterpret_cast<float*>(smem + OFF_BV);
    float* sbx   = reinterpret_cast<float*>(smem + OFF_BX);

    // per-warp constants
    const int arow  = 16*wid + (lane >> 1);   // act row this lane stages
    const int ahalf = lane & 1;
    const uint32_t a_act  = sbase + OFF_ACT  + (16*wid + (lane & 15)) * SA + 16 * (lane >> 4);
    const uint32_t a_wt   = sbase + OFF_S    + (16*wid + (lane & 15)) * SW + 16 * (lane >> 4);
    const uint32_t b_w1   = sbase + OFF_W1   + (lane & 15) * SA + 16 * (lane >> 4);
    const uint32_t b_w2a  = sbase + OFF_W2A  + (lane & 15) * SA + 16 * (lane >> 4);
    const uint32_t b_w2b  = sbase + OFF_W2B  + (lane & 15) * SW + 16 * (lane >> 4);
    const uint32_t b_d11  = sbase + OFF_D11B + (lane & 15) * SW + 16 * (lane >> 4);
    const int q  = lane & 3;
    const int rh = lane >> 2;

    // ---------- prefetch FIRST tile's act rows (overlaps weight copy) ----------
    float4 xr[8], ur[2];
    {
        const int row0 = blockIdx.x * MROWS + arow;
        const bool ok = row0 < N;
        const float4* gx4 = reinterpret_cast<const float4*>(gx) + (size_t)row0 * 16 + ahalf * 8;
        const float4* gu4 = reinterpret_cast<const float4*>(gu) + (size_t)row0 * 4  + ahalf * 2;
        #pragma unroll
        for (int i = 0; i < 8; i++) xr[i] = ok ? gx4[i] : make_float4(0,0,0,0);
        ur[0] = ok ? gu4[0] : make_float4(0,0,0,0);
        ur[1] = ok ? gu4[1] : make_float4(0,0,0,0);
    }

    // ---------- copy pre-split weights + biases (ONCE per CTA) ----------
    {
        const uint4* s1 = reinterpret_cast<const uint4*>(gW1s);
        const uint4* s2 = reinterpret_cast<const uint4*>(gW2As);
        uint4* d1 = reinterpret_cast<uint4*>(smem + OFF_W1);
        uint4* d2 = reinterpret_cast<uint4*>(smem + OFF_W2A);
        #pragma unroll 1
        for (int i = tid; i < 21504/16; i += NTHREADS) { d1[i] = s1[i]; d2[i] = s2[i]; }
        const uint4* s3 = reinterpret_cast<const uint4*>(gW2Bs);
        uint4* d3 = reinterpret_cast<uint4*>(smem + OFF_W2B);
        #pragma unroll 1
        for (int i = tid; i < 17408/16; i += NTHREADS) d3[i] = s3[i];
        const uint4* s4 = reinterpret_cast<const uint4*>(gD11Bs);
        uint4* d4 = reinterpret_cast<uint4*>(smem + OFF_D11B);
        #pragma unroll 1
        for (int i = tid; i < 13056/16; i += NTHREADS) d4[i] = s4[i];
        if (tid >= 64 && tid < 128)  sbv[tid - 64]  = gbv[tid - 64];
        if (tid >= 128 && tid < 192) sbx[tid - 128] = gbx[tid - 128];
    }
    __syncthreads();   // ONLY block-wide barrier in the kernel

    // ================= persistent tile loop (fully warp-local) =================
    #pragma unroll 1
    for (int t = blockIdx.x; t < nTiles; t += gridDim.x) {
        const int rowbase = t * MROWS;

        // ---- act rows for this tile (first tile uses prefetched regs) ----
        if (t != (int)blockIdx.x) {
            const int row0 = rowbase + arow;
            const bool ok = row0 < N;
            const float4* gx4 = reinterpret_cast<const float4*>(gx) + (size_t)row0 * 16 + ahalf * 8;
            const float4* gu4 = reinterpret_cast<const float4*>(gu) + (size_t)row0 * 4  + ahalf * 2;
            #pragma unroll
            for (int i = 0; i < 8; i++) xr[i] = ok ? gx4[i] : make_float4(0,0,0,0);
            ur[0] = ok ? gu4[0] : make_float4(0,0,0,0);
            ur[1] = ok ? gu4[1] : make_float4(0,0,0,0);
        }
        // ---- stage own act rows (warp-local, hi/lo split) ----
        {
            char* rp = smem + OFF_ACT + arow * SA;
            #pragma unroll
            for (int i = 0; i < 8; i++) {
                const int q0 = ahalf * 8 + i;
                unsigned h0, l0, h1, l1;
                split2(xr[i].x, xr[i].y, h0, l0);
                split2(xr[i].z, xr[i].w, h1, l1);
                *reinterpret_cast<uint2*>(rp + 8*q0)       = make_uint2(h0, h1);
                *reinterpret_cast<uint2*>(rp + 160 + 8*q0) = make_uint2(l0, l1);
            }
            #pragma unroll
            for (int j = 0; j < 2; j++) {
                const int q0 = ahalf * 2 + j;
                unsigned h0, l0, h1, l1;
                split2(ur[j].x, ur[j].y, h0, l0);
                split2(ur[j].z, ur[j].w, h1, l1);
                *reinterpret_cast<uint2*>(rp + 128 + 8*q0) = make_uint2(h0, h1);
                *reinterpret_cast<uint2*>(rp + 288 + 8*q0) = make_uint2(l0, l1);
            }
        }
        __syncwarp();

        // ===== GEMM1: base = [act] x W1^T (B-frag reuse); spill only block 0 =====
        float acc[8][4] = {};
        #pragma unroll
        for (int c = 0; c < 5; c++) {
            unsigned ah[4], al[4];
            ldsm4(ah, a_act + 32 * c);
            ldsm4(al, a_act + 32 * (5 + c));
            gemm_chunk_reuse(acc, b_w1 + 32*c, b_w1 + 32*(5+c), SA, ah, al);
        }
        #pragma unroll
        for (int n = 0; n < 2; n++) {               // only block-0 cols to stage
            const int c0 = 8*n + 2*q;
            *reinterpret_cast<float2*>(stage + (16*wid + rh    ) * 68 + c0) = make_float2(acc[n][0], acc[n][1]);
            *reinterpret_cast<float2*>(stage + (16*wid + rh + 8) * 68 + c0) = make_float2(acc[n][2], acc[n][3]);
        }
        __syncwarp();

        // ===== blocked triangular solve with ReLU =====
        #pragma unroll
        for (int b = 0; b < 4; b++) {
            if (lane < 16) {
                const int row = 16*wid + lane;
                float wv[16];
                const float4* srow = reinterpret_cast<const float4*>(stage + row * 68 + 16*b);
                const float4* bvp  = reinterpret_cast<const float4*>(sbv + 16*b);
                #pragma unroll
                for (int g = 0; g < 4; g++) {
                    const float4 s = srow[g], v = bvp[g];
                    wv[4*g+0] = s.x + v.x; wv[4*g+1] = s.y + v.y;
                    wv[4*g+2] = s.z + v.z; wv[4*g+3] = s.w + v.w;
                }
                wv[0] = fmaxf(wv[0], 0.0f);
                #pragma unroll
                for (int il = 1; il < 16; il++) {
                    const float4* dptr = reinterpret_cast<const float4*>(gD11 + (16*b + il) * 64 + 16*b);
                    float a0 = wv[il], a1 = 0.0f, a2 = 0.0f, a3 = 0.0f;
                    const int ng = (il + 3) >> 2;
                    #pragma unroll
                    for (int g = 0; g < 4; g++) {
                        if (g >= ng) break;                  // strict-lower zeros pad tail
                        const float4 d = dptr[g];
                        a0 = fmaf(d.x, wv[4*g+0], a0);
                        a1 = fmaf(d.y, wv[4*g+1], a1);
                        a2 = fmaf(d.z, wv[4*g+2], a2);
                        a3 = fmaf(d.w, wv[4*g+3], a3);
                    }
                    wv[il] = fmaxf((a0 + a1) + (a2 + a3), 0.0f);
                }
                // write w_b as bf16 [hi_b | lo_b] over the stage bytes just consumed
                char* wtp = smem + OFF_S + row * SW + 64*b;
                unsigned hp[8], lp[8];
                #pragma unroll
                for (int tt = 0; tt < 8; tt++) split2(wv[2*tt], wv[2*tt+1], hp[tt], lp[tt]);
                *reinterpret_cast<uint4*>(wtp)      = make_uint4(hp[0], hp[1], hp[2], hp[3]);
                *reinterpret_cast<uint4*>(wtp + 16) = make_uint4(hp[4], hp[5], hp[6], hp[7]);
                *reinterpret_cast<uint4*>(wtp + 32) = make_uint4(lp[0], lp[1], lp[2], lp[3]);
                *reinterpret_cast<uint4*>(wtp + 48) = make_uint4(lp[4], lp[5], lp[6], lp[7]);
            }
            __syncwarp();

            // --- HMMA update of remaining cols, then spill next block to stage ---
            if (b < 3) {
                unsigned ahi[4], alo[4];
                ldsm4(ahi, a_wt + 64*b);
                ldsm4(alo, a_wt + 64*b + 32);
                #pragma unroll
                for (int p = 1; p < 4; p++) {
                    if (p <= b) continue;             // compile-time trimmed
                    unsigned bh[4], bl[4];
                    const uint32_t bb = b_d11 + (p - 1) * 16 * SW;
                    ldsm4(bh, bb + 32*b);
                    mma16816(acc[2*p    ], ahi, bh[0], bh[2]);
                    mma16816(acc[2*p + 1], ahi, bh[1], bh[3]);
                    mma16816(acc[2*p    ], alo, bh[0], bh[2]);
                    mma16816(acc[2*p + 1], alo, bh[1], bh[3]);
                    ldsm4(bl, bb + 128 + 32*b);
                    mma16816(acc[2*p    ], ahi, bl[0], bl[2]);
                    mma16816(acc[2*p + 1], ahi, bl[1], bl[3]);
                }
                #pragma unroll
                for (int n = 2*(b+1); n <= 2*(b+1) + 1; n++) {
                    const int c0 = 8*n + 2*q;
                    *reinterpret_cast<float2*>(stage + (16*wid + rh    ) * 68 + c0) = make_float2(acc[n][0], acc[n][1]);
                    *reinterpret_cast<float2*>(stage + (16*wid + rh + 8) * 68 + c0) = make_float2(acc[n][2], acc[n][3]);
                }
                __syncwarp();
            }
        }
        __syncwarp();

        // ===== GEMM2: out = [act] x W2a^T + [w] x B1^T (B-frag reuse) =====
        float acc2[8][4] = {};
        #pragma unroll
        for (int c = 0; c < 5; c++) {
            unsigned ah[4], al[4];
            ldsm4(ah, a_act + 32 * c);
            ldsm4(al, a_act + 32 * (5 + c));
            gemm_chunk_reuse(acc2, b_w2a + 32*c, b_w2a + 32*(5+c), SA, ah, al);
        }
        #pragma unroll
        for (int c = 0; c < 4; c++) {
            unsigned wh[4], wl[4];
            ldsm4(wh, a_wt + 64*c);             // w hi chunk c (interleaved layout)
            ldsm4(wl, a_wt + 64*c + 32);        // w lo chunk c
            gemm_chunk_reuse(acc2, b_w2b + 32*c, b_w2b + 128 + 32*c, SW, wh, wl);
        }

        // ===== epilogue: +bx in registers, direct fragment stores =====
        #pragma unroll
        for (int n = 0; n < 8; n++) {
            const int col = 8*n + 2*q;
            const float2 bx2 = *reinterpret_cast<const float2*>(sbx + col);
            const int r0 = rowbase + 16*wid + rh;
            if (r0 < N)
                *reinterpret_cast<float2*>(gout + (size_t)r0 * 64 + col) =
                    make_float2(acc2[n][0] + bx2.x, acc2[n][1] + bx2.y);
            if (r0 + 8 < N)
                *reinterpret_cast<float2*>(gout + (size_t)(r0 + 8) * 64 + col) =
                    make_float2(acc2[n][2] + bx2.x, acc2[n][3] + bx2.y);
        }
        __syncwarp();   // wt/stage rows fully consumed before next tile reuses them
    }
}

extern "C" void kernel_launch(void* const* d_in, const int* in_sizes, int n_in,
                              void* d_out, int out_size) {
    (void)n_in; (void)out_size;
    const float* x   = (const float*)d_in[0];
    const float* u   = (const float*)d_in[1];
    const float* A   = (const float*)d_in[2];
    const float* B1  = (const float*)d_in[3];
    const float* B2  = (const float*)d_in[4];
    const float* C1  = (const float*)d_in[5];
    const float* D11 = (const float*)d_in[6];
    const float* D12 = (const float*)d_in[7];
    const float* bv  = (const float*)d_in[8];
    const float* bx  = (const float*)d_in[9];
    float* out = (float*)d_out;

    const int N = in_sizes[0] / 64;                     // 262144
    const int nTiles = (N + MROWS - 1) / MROWS;         // 1024
    const int grid = nTiles < 148 ? nTiles : 148;       // persistent: 1 CTA/SM

    renl2_prep_kernel<<<8, 128>>>(A, B1, B2, C1, D11, D12);

    cudaFuncSetAttribute(renl2_hmma_kernel,
                         cudaFuncAttributeMaxDynamicSharedMemorySize,
                         SMEM_BYTES);
    renl2_hmma_kernel<<<grid, NTHREADS, SMEM_BYTES>>>(
        x, u, D11, bv, bx, out, N, nTiles);
}

// round 17
// speedup vs baseline: 1.2805x; 1.0147x over previous
#include <cuda_runtime.h>
#include <cuda_bf16.h>
#include <cstdint>

#define NTHREADS 512
#define MROWS    256
#define SA 336            // act / W1 / W2a row stride in BYTES (168 bf16)
#define SW 272            // stage(f32x68) / wt / W2B / D11B row stride in BYTES

// ---------------- SMEM byte layout ----------------
#define OFF_W1    0        // bf16 [64 x 168]: C1_hi D12_hi | C1_lo D12_lo
#define OFF_W2A   21504    // bf16 [64 x 168]: A_hi  B2_hi  | A_lo  B2_lo
#define OFF_W2B   43008    // bf16 [64 x 136]: B1_hi | B1_lo
#define OFF_D11B  60416    // bf16 [48 x 136]: D11 rows 16..63, hi | lo
#define OFF_BV    73472    // f32 [64]
#define OFF_BX    73728    // f32 [64]
#define OFF_ACT   73984    // bf16 [256 x 168]: x_hi | u_hi | x_lo | u_lo
#define OFF_S     160000   // ALIASED: stage f32[256 x 68] / wt bf16 [hi_b|lo_b] at byte 64b
#define SMEM_BYTES 229632

__device__ __align__(16) unsigned char gW1s  [21504];
__device__ __align__(16) unsigned char gW2As [21504];
__device__ __align__(16) unsigned char gW2Bs [17408];
__device__ __align__(16) unsigned char gD11Bs[13056];

__device__ __forceinline__ uint32_t smem_u32(const void* p) {
    uint32_t a;
    asm("{ .reg .u64 t; cvta.to.shared.u64 t, %1; cvt.u32.u64 %0, t; }" : "=r"(a) : "l"(p));
    return a;
}
__device__ __forceinline__ void ldsm4(unsigned r[4], uint32_t addr) {
    asm volatile("ldmatrix.sync.aligned.m8n8.x4.shared.b16 {%0,%1,%2,%3}, [%4];"
        : "=r"(r[0]), "=r"(r[1]), "=r"(r[2]), "=r"(r[3]) : "r"(addr));
}
__device__ __forceinline__ void mma16816(float* d, const unsigned* a, unsigned b0, unsigned b1) {
    asm volatile("mma.sync.aligned.m16n8k16.row.col.f32.bf16.bf16.f32 "
        "{%0,%1,%2,%3},{%4,%5,%6,%7},{%8,%9},{%0,%1,%2,%3};"
        : "+f"(d[0]), "+f"(d[1]), "+f"(d[2]), "+f"(d[3])
        : "r"(a[0]), "r"(a[1]), "r"(a[2]), "r"(a[3]), "r"(b0), "r"(b1));
}
__device__ __forceinline__ void split2(float a, float b, unsigned& hi, unsigned& lo) {
    const __nv_bfloat16 ha = __float2bfloat16_rn(a), hb = __float2bfloat16_rn(b);
    hi = (unsigned)(*reinterpret_cast<const unsigned short*>(&ha))
       | ((unsigned)(*reinterpret_cast<const unsigned short*>(&hb)) << 16);
    const __nv_bfloat162 t = __floats2bfloat162_rn(a - __bfloat162float(ha),
                                                   b - __bfloat162float(hb));
    lo = *reinterpret_cast<const unsigned*>(&t);
}
// one chunk of a 3-product split GEMM with B-fragment register reuse:
//   acc += ah x Bhi (hi.hi), al x Bhi (lo.hi), ah x Blo (hi.lo)
__device__ __forceinline__ void gemm_chunk_reuse(float (*acc)[4], uint32_t b_hi, uint32_t b_lo,
                                                 int strideB, const unsigned ah[4], const unsigned al[4]) {
    #pragma unroll
    for (int p = 0; p < 4; p++) {
        unsigned bh[4];
        ldsm4(bh, b_hi + p * 16 * strideB);
        mma16816(acc[2*p + 0], ah, bh[0], bh[2]);
        mma16816(acc[2*p + 1], ah, bh[1], bh[3]);
        mma16816(acc[2*p + 0], al, bh[0], bh[2]);
        mma16816(acc[2*p + 1], al, bh[1], bh[3]);
        unsigned bl[4];
        ldsm4(bl, b_lo + p * 16 * strideB);
        mma16816(acc[2*p + 0], ah, bl[0], bl[2]);
        mma16816(acc[2*p + 1], ah, bl[1], bl[3]);
    }
}

// ---------------- prep kernel (8 CTAs) ----------------
__global__ void __launch_bounds__(128)
renl2_prep_kernel(const float* __restrict__ gA,  const float* __restrict__ gB1,
                  const float* __restrict__ gB2, const float* __restrict__ gC1,
                  const float* __restrict__ gD11,const float* __restrict__ gD12)
{
    const int tid = blockIdx.x * 128 + threadIdx.x;
    #pragma unroll 1
    for (int idx = tid; idx < 64 * 40; idx += 1024) {
        const int n = idx / 40, k = (idx - n * 40) * 2;
        float v1a, v1b, v2a, v2b;
        if (k < 64) { v1a = gC1[n*64 + k]; v1b = gC1[n*64 + k + 1];
                      v2a = gA [n*64 + k]; v2b = gA [n*64 + k + 1]; }
        else        { v1a = gD12[n*16 + k - 64]; v1b = gD12[n*16 + k - 63];
                      v2a = gB2 [n*16 + k - 64]; v2b = gB2 [n*16 + k - 63]; }
        unsigned h1, l1, h2, l2;
        split2(v1a, v1b, h1, l1);
        split2(v2a, v2b, h2, l2);
        *reinterpret_cast<unsigned*>(gW1s  + n*SA + 2*k)       = h1;
        *reinterpret_cast<unsigned*>(gW1s  + n*SA + 160 + 2*k) = l1;
        *reinterpret_cast<unsigned*>(gW2As + n*SA + 2*k)       = h2;
        *reinterpret_cast<unsigned*>(gW2As + n*SA + 160 + 2*k) = l2;
    }
    #pragma unroll 1
    for (int idx = tid; idx < 64 * 32; idx += 1024) {
        const int n = idx >> 5, k = (idx & 31) * 2;
        unsigned h, l;
        split2(gB1[n*64 + k], gB1[n*64 + k + 1], h, l);
        *reinterpret_cast<unsigned*>(gW2Bs + n*SW + 2*k)       = h;
        *reinterpret_cast<unsigned*>(gW2Bs + n*SW + 128 + 2*k) = l;
    }
    #pragma unroll 1
    for (int idx = tid; idx < 48 * 32; idx += 1024) {
        const int nl = idx >> 5, k = (idx & 31) * 2, n = nl + 16;
        unsigned h, l;
        split2(gD11[n*64 + k], gD11[n*64 + k + 1], h, l);
        *reinterpret_cast<unsigned*>(gD11Bs + nl*SW + 2*k)       = h;
        *reinterpret_cast<unsigned*>(gD11Bs + nl*SW + 128 + 2*k) = l;
    }
}

// ---------------- main kernel: persistent CTAs, pipelined act prefetch ----------------
__global__ void __launch_bounds__(NTHREADS, 1)
renl2_hmma_kernel(const float* __restrict__ gx,  const float* __restrict__ gu,
                  const float* __restrict__ gD11,
                  const float* __restrict__ gbv, const float* __restrict__ gbx,
                  float* __restrict__ gout, int N, int nTiles)
{
    extern __shared__ char smem[];
    const uint32_t sbase = smem_u32(smem);
    const int tid  = threadIdx.x;
    const int lane = tid & 31;
    const int wid  = tid >> 5;

    float* stage = reinterpret_cast<float*>(smem + OFF_S);    // aliased with wt
    float* sbv   = reinterpret_cast<float*>(smem + OFF_BV);
    float* sbx   = reinterpret_cast<float*>(smem + OFF_BX);

    // per-warp constants
    const int arow  = 16*wid + (lane >> 1);   // act row this lane stages
    const int ahalf = lane & 1;
    const uint32_t a_act  = sbase + OFF_ACT  + (16*wid + (lane & 15)) * SA + 16 * (lane >> 4);
    const uint32_t a_wt   = sbase + OFF_S    + (16*wid + (lane & 15)) * SW + 16 * (lane >> 4);
    const uint32_t b_w1   = sbase + OFF_W1   + (lane & 15) * SA + 16 * (lane >> 4);
    const uint32_t b_w2a  = sbase + OFF_W2A  + (lane & 15) * SA + 16 * (lane >> 4);
    const uint32_t b_w2b  = sbase + OFF_W2B  + (lane & 15) * SW + 16 * (lane >> 4);
    const uint32_t b_d11  = sbase + OFF_D11B + (lane & 15) * SW + 16 * (lane >> 4);
    const int q  = lane & 3;
    const int rh = lane >> 2;

    // ---------- prefetch FIRST tile's act rows (overlaps weight copy) ----------
    float4 xr[8], ur[2];
    {
        const int row0 = blockIdx.x * MROWS + arow;
        const bool ok = row0 < N;
        const float4* gx4 = reinterpret_cast<const float4*>(gx) + (size_t)row0 * 16 + ahalf * 8;
        const float4* gu4 = reinterpret_cast<const float4*>(gu) + (size_t)row0 * 4  + ahalf * 2;
        #pragma unroll
        for (int i = 0; i < 8; i++) xr[i] = ok ? gx4[i] : make_float4(0,0,0,0);
        ur[0] = ok ? gu4[0] : make_float4(0,0,0,0);
        ur[1] = ok ? gu4[1] : make_float4(0,0,0,0);
    }

    // ---------- copy pre-split weights + biases (ONCE per CTA) ----------
    {
        const uint4* s1 = reinterpret_cast<const uint4*>(gW1s);
        const uint4* s2 = reinterpret_cast<const uint4*>(gW2As);
        uint4* d1 = reinterpret_cast<uint4*>(smem + OFF_W1);
        uint4* d2 = reinterpret_cast<uint4*>(smem + OFF_W2A);
        #pragma unroll 1
        for (int i = tid; i < 21504/16; i += NTHREADS) { d1[i] = s1[i]; d2[i] = s2[i]; }
        const uint4* s3 = reinterpret_cast<const uint4*>(gW2Bs);
        uint4* d3 = reinterpret_cast<uint4*>(smem + OFF_W2B);
        #pragma unroll 1
        for (int i = tid; i < 17408/16; i += NTHREADS) d3[i] = s3[i];
        const uint4* s4 = reinterpret_cast<const uint4*>(gD11Bs);
        uint4* d4 = reinterpret_cast<uint4*>(smem + OFF_D11B);
        #pragma unroll 1
        for (int i = tid; i < 13056/16; i += NTHREADS) d4[i] = s4[i];
        if (tid >= 64 && tid < 128)  sbv[tid - 64]  = gbv[tid - 64];
        if (tid >= 128 && tid < 192) sbx[tid - 128] = gbx[tid - 128];
    }
    __syncthreads();   // ONLY block-wide barrier in the kernel

    // ================= persistent tile loop (fully warp-local) =================
    #pragma unroll 1
    for (int t = blockIdx.x; t < nTiles; t += gridDim.x) {
        const int rowbase = t * MROWS;

        // ---- stage own act rows from prefetched registers (warp-local) ----
        {
            char* rp = smem + OFF_ACT + arow * SA;
            #pragma unroll
            for (int i = 0; i < 8; i++) {
                const int q0 = ahalf * 8 + i;
                unsigned h0, l0, h1, l1;
                split2(xr[i].x, xr[i].y, h0, l0);
                split2(xr[i].z, xr[i].w, h1, l1);
                *reinterpret_cast<uint2*>(rp + 8*q0)       = make_uint2(h0, h1);
                *reinterpret_cast<uint2*>(rp + 160 + 8*q0) = make_uint2(l0, l1);
            }
            #pragma unroll
            for (int j = 0; j < 2; j++) {
                const int q0 = ahalf * 2 + j;
                unsigned h0, l0, h1, l1;
                split2(ur[j].x, ur[j].y, h0, l0);
                split2(ur[j].z, ur[j].w, h1, l1);
                *reinterpret_cast<uint2*>(rp + 128 + 8*q0) = make_uint2(h0, h1);
                *reinterpret_cast<uint2*>(rp + 288 + 8*q0) = make_uint2(l0, l1);
            }
        }
        __syncwarp();

        // ===== GEMM1: base = [act] x W1^T (B-frag reuse); spill only block 0 =====
        float acc[8][4] = {};
        #pragma unroll
        for (int c = 0; c < 5; c++) {
            unsigned ah[4], al[4];
            ldsm4(ah, a_act + 32 * c);
            ldsm4(al, a_act + 32 * (5 + c));
            gemm_chunk_reuse(acc, b_w1 + 32*c, b_w1 + 32*(5+c), SA, ah, al);
        }
        #pragma unroll
        for (int n = 0; n < 2; n++) {               // only block-0 cols to stage
            const int c0 = 8*n + 2*q;
            *reinterpret_cast<float2*>(stage + (16*wid + rh    ) * 68 + c0) = make_float2(acc[n][0], acc[n][1]);
            *reinterpret_cast<float2*>(stage + (16*wid + rh + 8) * 68 + c0) = make_float2(acc[n][2], acc[n][3]);
        }
        __syncwarp();

        // ---- PIPELINED PREFETCH: next tile's act rows (hidden by solve + GEMM2) ----
        {
            const int t2 = t + gridDim.x;
            if (t2 < nTiles) {
                const int row0 = t2 * MROWS + arow;
                const bool ok = row0 < N;
                const float4* gx4 = reinterpret_cast<const float4*>(gx) + (size_t)row0 * 16 + ahalf * 8;
                const float4* gu4 = reinterpret_cast<const float4*>(gu) + (size_t)row0 * 4  + ahalf * 2;
                #pragma unroll
                for (int i = 0; i < 8; i++) xr[i] = ok ? gx4[i] : make_float4(0,0,0,0);
                ur[0] = ok ? gu4[0] : make_float4(0,0,0,0);
                ur[1] = ok ? gu4[1] : make_float4(0,0,0,0);
            }
        }

        // ===== blocked triangular solve with ReLU =====
        #pragma unroll
        for (int b = 0; b < 4; b++) {
            if (lane < 16) {
                const int row = 16*wid + lane;
                float wv[16];
                const float4* srow = reinterpret_cast<const float4*>(stage + row * 68 + 16*b);
                const float4* bvp  = reinterpret_cast<const float4*>(sbv + 16*b);
                #pragma unroll
                for (int g = 0; g < 4; g++) {
                    const float4 s = srow[g], v = bvp[g];
                    wv[4*g+0] = s.x + v.x; wv[4*g+1] = s.y + v.y;
                    wv[4*g+2] = s.z + v.z; wv[4*g+3] = s.w + v.w;
                }
                wv[0] = fmaxf(wv[0], 0.0f);
                #pragma unroll
                for (int il = 1; il < 16; il++) {
                    const float4* dptr = reinterpret_cast<const float4*>(gD11 + (16*b + il) * 64 + 16*b);
                    float a0 = wv[il], a1 = 0.0f, a2 = 0.0f, a3 = 0.0f;
                    const int ng = (il + 3) >> 2;
                    #pragma unroll
                    for (int g = 0; g < 4; g++) {
                        if (g >= ng) break;                  // strict-lower zeros pad tail
                        const float4 d = dptr[g];
                        a0 = fmaf(d.x, wv[4*g+0], a0);
                        a1 = fmaf(d.y, wv[4*g+1], a1);
                        a2 = fmaf(d.z, wv[4*g+2], a2);
                        a3 = fmaf(d.w, wv[4*g+3], a3);
                    }
                    wv[il] = fmaxf((a0 + a1) + (a2 + a3), 0.0f);
                }
                // write w_b as bf16 [hi_b | lo_b] over the stage bytes just consumed
                char* wtp = smem + OFF_S + row * SW + 64*b;
                unsigned hp[8], lp[8];
                #pragma unroll
                for (int tt = 0; tt < 8; tt++) split2(wv[2*tt], wv[2*tt+1], hp[tt], lp[tt]);
                *reinterpret_cast<uint4*>(wtp)      = make_uint4(hp[0], hp[1], hp[2], hp[3]);
                *reinterpret_cast<uint4*>(wtp + 16) = make_uint4(hp[4], hp[5], hp[6], hp[7]);
                *reinterpret_cast<uint4*>(wtp + 32) = make_uint4(lp[0], lp[1], lp[2], lp[3]);
                *reinterpret_cast<uint4*>(wtp + 48) = make_uint4(lp[4], lp[5], lp[6], lp[7]);
            }
            __syncwarp();

            // --- HMMA update of remaining cols, then spill next block to stage ---
            if (b < 3) {
                unsigned ahi[4], alo[4];
                ldsm4(ahi, a_wt + 64*b);
                ldsm4(alo, a_wt + 64*b + 32);
                #pragma unroll
                for (int p = 1; p < 4; p++) {
                    if (p <= b) continue;             // compile-time trimmed
                    unsigned bh[4], bl[4];
                    const uint32_t bb = b_d11 + (p - 1) * 16 * SW;
                    ldsm4(bh, bb + 32*b);
                    mma16816(acc[2*p    ], ahi, bh[0], bh[2]);
                    mma16816(acc[2*p + 1], ahi, bh[1], bh[3]);
                    mma16816(acc[2*p    ], alo, bh[0], bh[2]);
                    mma16816(acc[2*p + 1], alo, bh[1], bh[3]);
                    ldsm4(bl, bb + 128 + 32*b);
                    mma16816(acc[2*p    ], ahi, bl[0], bl[2]);
                    mma16816(acc[2*p + 1], ahi, bl[1], bl[3]);
                }
                #pragma unroll
                for (int n = 2*(b+1); n <= 2*(b+1) + 1; n++) {
                    const int c0 = 8*n + 2*q;
                    *reinterpret_cast<float2*>(stage + (16*wid + rh    ) * 68 + c0) = make_float2(acc[n][0], acc[n][1]);
                    *reinterpret_cast<float2*>(stage + (16*wid + rh + 8) * 68 + c0) = make_float2(acc[n][2], acc[n][3]);
                }
                __syncwarp();
            }
        }
        __syncwarp();

        // ===== GEMM2: out = [act] x W2a^T + [w] x B1^T (B-frag reuse) =====
        float acc2[8][4] = {};
        #pragma unroll
        for (int c = 0; c < 5; c++) {
            unsigned ah[4], al[4];
            ldsm4(ah, a_act + 32 * c);
            ldsm4(al, a_act + 32 * (5 + c));
            gemm_chunk_reuse(acc2, b_w2a + 32*c, b_w2a + 32*(5+c), SA, ah, al);
        }
        #pragma unroll
        for (int c = 0; c < 4; c++) {
            unsigned wh[4], wl[4];
            ldsm4(wh, a_wt + 64*c);             // w hi chunk c (interleaved layout)
            ldsm4(wl, a_wt + 64*c + 32);        // w lo chunk c
            gemm_chunk_reuse(acc2, b_w2b + 32*c, b_w2b + 128 + 32*c, SW, wh, wl);
        }

        // ===== epilogue: +bx in registers, direct fragment stores =====
        #pragma unroll
        for (int n = 0; n < 8; n++) {
            const int col = 8*n + 2*q;
            const float2 bx2 = *reinterpret_cast<const float2*>(sbx + col);
            const int r0 = rowbase + 16*wid + rh;
            if (r0 < N)
                *reinterpret_cast<float2*>(gout + (size_t)r0 * 64 + col) =
                    make_float2(acc2[n][0] + bx2.x, acc2[n][1] + bx2.y);
            if (r0 + 8 < N)
                *reinterpret_cast<float2*>(gout + (size_t)(r0 + 8) * 64 + col) =
                    make_float2(acc2[n][2] + bx2.x, acc2[n][3] + bx2.y);
        }
        __syncwarp();   // wt/stage rows fully consumed before next tile reuses them
    }
}

extern "C" void kernel_launch(void* const* d_in, const int* in_sizes, int n_in,
                              void* d_out, int out_size) {
    (void)n_in; (void)out_size;
    const float* x   = (const float*)d_in[0];
    const float* u   = (const float*)d_in[1];
    const float* A   = (const float*)d_in[2];
    const float* B1  = (const float*)d_in[3];
    const float* B2  = (const float*)d_in[4];
    const float* C1  = (const float*)d_in[5];
    const float* D11 = (const float*)d_in[6];
    const float* D12 = (const float*)d_in[7];
    const float* bv  = (const float*)d_in[8];
    const float* bx  = (const float*)d_in[9];
    float* out = (float*)d_out;

    const int N = in_sizes[0] / 64;                     // 262144
    const int nTiles = (N + MROWS - 1) / MROWS;         // 1024
    const int grid = nTiles < 148 ? nTiles : 148;       // persistent: 1 CTA/SM

    renl2_prep_kernel<<<8, 128>>>(A, B1, B2, C1, D11, D12);

    cudaFuncSetAttribute(renl2_hmma_kernel,
                         cudaFuncAttributeMaxDynamicSharedMemorySize,
                         SMEM_BYTES);
    renl2_hmma_kernel<<<grid, NTHREADS, SMEM_BYTES>>>(
        x, u, D11, bv, bx, out, N, nTiles);
}